// round 2
// baseline (speedup 1.0000x reference)
#include <cuda_runtime.h>
#include <math.h>

#define SEQ   2048
#define DIM   2048
#define NH    16
#define QLR   768
#define KVLR  512
#define DN    128
#define DR    64
#define DV    128
#define QKH   192
#define HALF  96

#define SCALEF 0.0721687836487032f           // 192^-0.5
#define LAMBDA_INIT_F 0.556058204155754f     // 0.8 - 0.6*exp(-0.9)
#define ONE_MINUS_LI  0.443941795844246f

// ---------------- scratch (no allocations allowed) ----------------
__device__ float g_qa[SEQ * QLR];            // x @ wq_a^T
__device__ float g_q[SEQ * NH * QKH];        // q (roped in place)
__device__ float g_kvfull[SEQ * (KVLR + DR)];
__device__ float g_kvb[SEQ * NH * (DN + DV)];
__device__ float g_kpe[SEQ * DR];            // roped shared k_pe
__device__ float g_attn[SEQ * NH * DV];      // attention output, [s][h*128+d]
__device__ float g_lam;

// ---------------- GEMM: C[M,N] = A[M,K] @ B[N,K]^T (both row-major) ----------------
// 128x128 tile, BK=8, 256 threads, 8x8 microtile.
__global__ __launch_bounds__(256) void gemm_nt(
    const float* __restrict__ A, const float* __restrict__ B, float* __restrict__ C,
    int M, int N, int K, int lda, int ldb, int ldc)
{
    __shared__ float As[8][132];
    __shared__ float Bs[8][132];

    const int tid = threadIdx.x;
    const int m0 = blockIdx.y * 128;
    const int n0 = blockIdx.x * 128;

    const int lrow = tid >> 1;        // 0..127
    const int kc   = (tid & 1) * 4;   // 0 or 4
    const int ty   = tid >> 4;        // 0..15 -> rows ty*8
    const int tx   = tid & 15;        // 0..15 -> cols tx*8

    float acc[8][8];
#pragma unroll
    for (int i = 0; i < 8; i++)
#pragma unroll
        for (int j = 0; j < 8; j++) acc[i][j] = 0.f;

    const bool bvalid = (n0 + lrow) < N;
    const float* Aptr = A + (long)(m0 + lrow) * lda + kc;
    const float* Bptr = B + (long)(n0 + lrow) * ldb + kc;

    for (int kt = 0; kt < K; kt += 8) {
        float4 a = *(const float4*)(Aptr + kt);
        float4 b = bvalid ? *(const float4*)(Bptr + kt) : make_float4(0.f, 0.f, 0.f, 0.f);
        As[kc + 0][lrow] = a.x; As[kc + 1][lrow] = a.y;
        As[kc + 2][lrow] = a.z; As[kc + 3][lrow] = a.w;
        Bs[kc + 0][lrow] = b.x; Bs[kc + 1][lrow] = b.y;
        Bs[kc + 2][lrow] = b.z; Bs[kc + 3][lrow] = b.w;
        __syncthreads();

#pragma unroll
        for (int kk = 0; kk < 8; kk++) {
            float av[8], bv[8];
            *(float4*)&av[0] = *(const float4*)&As[kk][ty * 8];
            *(float4*)&av[4] = *(const float4*)&As[kk][ty * 8 + 4];
            *(float4*)&bv[0] = *(const float4*)&Bs[kk][tx * 8];
            *(float4*)&bv[4] = *(const float4*)&Bs[kk][tx * 8 + 4];
#pragma unroll
            for (int i = 0; i < 8; i++)
#pragma unroll
                for (int j = 0; j < 8; j++)
                    acc[i][j] += av[i] * bv[j];
        }
        __syncthreads();
    }

#pragma unroll
    for (int i = 0; i < 8; i++) {
        const int m = m0 + ty * 8 + i;
        const int nbase = n0 + tx * 8;
        if (nbase < N) {
            *(float4*)&C[(long)m * ldc + nbase] =
                make_float4(acc[i][0], acc[i][1], acc[i][2], acc[i][3]);
            *(float4*)&C[(long)m * ldc + nbase + 4] =
                make_float4(acc[i][4], acc[i][5], acc[i][6], acc[i][7]);
        }
    }
}

// ---------------- RoPE (interleaved pairs) ----------------
__global__ void rope_kernel(float* __restrict__ q, const float* __restrict__ kvfull,
                            float* __restrict__ kpe,
                            const float* __restrict__ cosb, const float* __restrict__ sinb)
{
    const int s = blockIdx.x;
    for (int idx = threadIdx.x; idx < NH * 32 + 32; idx += blockDim.x) {
        if (idx < NH * 32) {
            const int h = idx >> 5, p = idx & 31;
            const float c = cosb[s * 32 + p], sn = sinb[s * 32 + p];
            float* base = q + (long)s * (NH * QKH) + h * QKH + DN;
            const float xr = base[2 * p], xi = base[2 * p + 1];
            base[2 * p]     = xr * c - xi * sn;
            base[2 * p + 1] = xr * sn + xi * c;
        } else {
            const int p = idx - NH * 32;
            const float c = cosb[s * 32 + p], sn = sinb[s * 32 + p];
            const float* kb = kvfull + (long)s * (KVLR + DR) + KVLR;
            const float xr = kb[2 * p], xi = kb[2 * p + 1];
            kpe[s * DR + 2 * p]     = xr * c - xi * sn;
            kpe[s * DR + 2 * p + 1] = xr * sn + xi * c;
        }
    }
}

// ---------------- lambda scalar ----------------
__global__ void lam_kernel(const float* __restrict__ lqn, const float* __restrict__ lqr,
                           const float* __restrict__ lkn, const float* __restrict__ lkr)
{
    if (threadIdx.x == 0) {
        float d1 = 0.f, d2 = 0.f;
        for (int i = 0; i < DN; i++) d1 += lqn[i] * lkn[i];
        for (int i = 0; i < DR; i++) d2 += lqr[i] * lkr[i];
        g_lam = expf(d1) - expf(d2) + LAMBDA_INIT_F;
    }
}

// ---------------- fused dual-softmax flash attention ----------------
// grid (SEQ/64, NH), 256 threads. BQ=64, BK=32.
#define BQ 64
#define BK 32
#define QS_STRIDE 196
#define KS_STRIDE 33

#define SM_QS 0
#define SM_K1 (SM_QS + BQ * QS_STRIDE)           // 12544
#define SM_K2 (SM_K1 + HALF * KS_STRIDE)         // +3168
#define SM_VS (SM_K2 + HALF * KS_STRIDE)         // +3168
#define SM_S1 (SM_VS + BK * DV)                  // +4096
#define SM_S2 (SM_S1 + BQ * KS_STRIDE)           // +2112
#define SM_R1 (SM_S2 + BQ * KS_STRIDE)           // +2112
#define SM_R2 (SM_R1 + BQ * 4)                   // +256
#define SM_TOTAL (SM_R2 + BQ * 4)                // 27712 floats = 110848 B

__global__ __launch_bounds__(256, 2) void attn_kernel(
    const float* __restrict__ q, const float* __restrict__ kvb,
    const float* __restrict__ kpe, float* __restrict__ attn_out)
{
    extern __shared__ float sm[];
    float* Qs = sm + SM_QS;
    float* K1 = sm + SM_K1;
    float* K2 = sm + SM_K2;
    float* Vs = sm + SM_VS;
    float* S1 = sm + SM_S1;
    float* S2 = sm + SM_S2;
    float* R1 = sm + SM_R1;
    float* R2 = sm + SM_R2;

    const int tid = threadIdx.x;
    const int h = blockIdx.y;
    const int s0 = blockIdx.x * BQ;

    // load Q tile [64 x 192]
    for (int idx = tid; idx < BQ * QKH; idx += 256) {
        const int r = idx / QKH, c = idx - r * QKH;
        Qs[r * QS_STRIDE + c] = q[(long)(s0 + r) * (NH * QKH) + h * QKH + c];
    }
    const float lam = g_lam;

    const int row = tid >> 2, quad = tid & 3;  // softmax/accum mapping
    const int rg = tid >> 3, kg = tid & 7;     // score mapping: rows rg*2.., keys kg*4..

    float m1 = -1e30f, m2 = -1e30f, l1 = 0.f, l2 = 0.f;
    float o1[32], o2[32];
#pragma unroll
    for (int d = 0; d < 32; d++) { o1[d] = 0.f; o2[d] = 0.f; }

    __syncthreads();

    const int tend = s0 + BQ - 1;
    for (int t0 = 0; t0 <= tend; t0 += BK) {
        // ---- load K/V tile ----
        for (int idx = tid; idx < BK * 256; idx += 256) {
            const int tl = idx >> 8, c = idx & 255;
            const float v = kvb[(long)(t0 + tl) * (NH * 256) + h * 256 + c];
            if (c < HALF)       K1[c * KS_STRIDE + tl] = v;
            else if (c < DN)    K2[(c - HALF) * KS_STRIDE + tl] = v;
            else                Vs[tl * DV + (c - DN)] = v;
        }
        for (int idx = tid; idx < BK * DR; idx += 256) {
            const int tl = idx >> 6, c = idx & 63;
            K2[(32 + c) * KS_STRIDE + tl] = kpe[(t0 + tl) * DR + c];
        }
        __syncthreads();

        // ---- scores: 2 rows x 4 keys per thread ----
        {
            float a1[2][4], a2[2][4];
#pragma unroll
            for (int i = 0; i < 2; i++)
#pragma unroll
                for (int j = 0; j < 4; j++) { a1[i][j] = 0.f; a2[i][j] = 0.f; }
            const float* q0 = &Qs[(rg * 2) * QS_STRIDE];
            const float* q1 = &Qs[(rg * 2 + 1) * QS_STRIDE];
#pragma unroll 4
            for (int c = 0; c < HALF; c++) {
                const float qa = q0[c], qb = q1[c];
                const float qa2 = q0[HALF + c], qb2 = q1[HALF + c];
#pragma unroll
                for (int j = 0; j < 4; j++) {
                    const float k1v = K1[c * KS_STRIDE + kg * 4 + j];
                    const float k2v = K2[c * KS_STRIDE + kg * 4 + j];
                    a1[0][j] += qa * k1v;  a1[1][j] += qb * k1v;
                    a2[0][j] += qa2 * k2v; a2[1][j] += qb2 * k2v;
                }
            }
#pragma unroll
            for (int i = 0; i < 2; i++) {
                const int r = rg * 2 + i;
#pragma unroll
                for (int j = 0; j < 4; j++) {
                    const int k = kg * 4 + j;
                    float v1 = fminf(fmaxf(a1[i][j] * SCALEF, -100.f), 100.f);
                    float v2 = fminf(fmaxf(a2[i][j] * SCALEF, -100.f), 100.f);
                    if (t0 + k > s0 + r) { v1 = -1e9f; v2 = -1e9f; }
                    S1[r * KS_STRIDE + k] = v1;
                    S2[r * KS_STRIDE + k] = v2;
                }
            }
        }
        __syncthreads();

        // ---- partial max over own 8 keys ----
        float pm1 = -1e30f, pm2 = -1e30f;
#pragma unroll
        for (int j = 0; j < 8; j++) {
            const int k = quad * 8 + j;
            pm1 = fmaxf(pm1, S1[row * KS_STRIDE + k]);
            pm2 = fmaxf(pm2, S2[row * KS_STRIDE + k]);
        }
        R1[row * 4 + quad] = pm1;
        R2[row * 4 + quad] = pm2;
        __syncthreads();

        float m1n = m1, m2n = m2;
#pragma unroll
        for (int j = 0; j < 4; j++) {
            m1n = fmaxf(m1n, R1[row * 4 + j]);
            m2n = fmaxf(m2n, R2[row * 4 + j]);
        }

        // ---- p = exp(s - m), written back in place; partial sums ----
        float ps1 = 0.f, ps2 = 0.f;
#pragma unroll
        for (int j = 0; j < 8; j++) {
            const int k = quad * 8 + j;
            const float p1 = __expf(S1[row * KS_STRIDE + k] - m1n);
            const float p2 = __expf(S2[row * KS_STRIDE + k] - m2n);
            S1[row * KS_STRIDE + k] = p1;
            S2[row * KS_STRIDE + k] = p2;
            ps1 += p1; ps2 += p2;
        }
        __syncthreads();     // everyone done reading R for maxes
        R1[row * 4 + quad] = ps1;
        R2[row * 4 + quad] = ps2;
        __syncthreads();

        float ts1 = 0.f, ts2 = 0.f;
#pragma unroll
        for (int j = 0; j < 4; j++) { ts1 += R1[row * 4 + j]; ts2 += R2[row * 4 + j]; }
        const float sc1 = __expf(m1 - m1n);
        const float sc2 = __expf(m2 - m2n);
        l1 = l1 * sc1 + ts1;
        l2 = l2 * sc2 + ts2;
        m1 = m1n; m2 = m2n;

#pragma unroll
        for (int d = 0; d < 32; d++) { o1[d] *= sc1; o2[d] *= sc2; }

        // ---- accumulate P @ V (thread dims strided by 4 -> conflict-free V reads) ----
#pragma unroll 4
        for (int k = 0; k < BK; k++) {
            const float p1 = S1[row * KS_STRIDE + k];
            const float p2 = S2[row * KS_STRIDE + k];
#pragma unroll
            for (int d = 0; d < 32; d++) {
                const float v = Vs[k * DV + quad + 4 * d];
                o1[d] += p1 * v;
                o2[d] += p2 * v;
            }
        }
        __syncthreads();     // smem reused by next tile's loads
    }

    const float i1 = 1.f / l1;
    const float i2 = lam / l2;
    float* outp = &attn_out[(long)(s0 + row) * (NH * DV) + h * DV + quad];
#pragma unroll
    for (int d = 0; d < 32; d++)
        outp[4 * d] = (o1[d] * i1 - o2[d] * i2) * ONE_MINUS_LI;
}

// ---------------- launch ----------------
extern "C" void kernel_launch(void* const* d_in, const int* in_sizes, int n_in,
                              void* d_out, int out_size)
{
    const float* x     = (const float*)d_in[0];
    const float* wq_a  = (const float*)d_in[1];
    const float* wq_b  = (const float*)d_in[2];
    const float* wkv_a = (const float*)d_in[3];
    const float* wkv_b = (const float*)d_in[4];
    const float* wo    = (const float*)d_in[5];
    const float* lqn   = (const float*)d_in[6];
    const float* lqr   = (const float*)d_in[7];
    const float* lkn   = (const float*)d_in[8];
    const float* lkr   = (const float*)d_in[9];
    const float* fcos  = (const float*)d_in[10];
    const float* fsin  = (const float*)d_in[11];
    // d_in[12] = mask (implemented analytically), d_in[13] = start_pos (== 0)
    float* out = (float*)d_out;

    float *qa, *qb, *kvf, *kvb, *kpe, *attn;
    cudaGetSymbolAddress((void**)&qa,   g_qa);
    cudaGetSymbolAddress((void**)&qb,   g_q);
    cudaGetSymbolAddress((void**)&kvf,  g_kvfull);
    cudaGetSymbolAddress((void**)&kvb,  g_kvb);
    cudaGetSymbolAddress((void**)&kpe,  g_kpe);
    cudaGetSymbolAddress((void**)&attn, g_attn);

    const dim3 blk(256);

    // q_a = x @ wq_a^T                      [2048 x 768]
    gemm_nt<<<dim3(QLR / 128, SEQ / 128), blk>>>(x, wq_a, qa, SEQ, QLR, DIM, DIM, DIM, QLR);
    // q = q_a @ wq_b^T                      [2048 x 3072]
    gemm_nt<<<dim3((NH * QKH) / 128, SEQ / 128), blk>>>(qa, wq_b, qb, SEQ, NH * QKH, QLR, QLR, QLR, NH * QKH);
    // kv_full = x @ wkv_a^T                 [2048 x 576]
    gemm_nt<<<dim3((KVLR + DR + 127) / 128, SEQ / 128), blk>>>(x, wkv_a, kvf, SEQ, KVLR + DR, DIM, DIM, DIM, KVLR + DR);
    // RoPE on q_pe (in place) and k_pe -> g_kpe
    rope_kernel<<<SEQ, 256>>>(qb, kvf, kpe, fcos, fsin);
    // kvb = kv_full[:, :512] @ wkv_b^T      [2048 x 4096]
    gemm_nt<<<dim3((NH * (DN + DV)) / 128, SEQ / 128), blk>>>(kvf, wkv_b, kvb, SEQ, NH * (DN + DV), KVLR, KVLR + DR, KVLR, NH * (DN + DV));
    // lambda scalar
    lam_kernel<<<1, 32>>>(lqn, lqr, lkn, lkr);
    // fused dual-softmax attention
    const int smem_bytes = SM_TOTAL * (int)sizeof(float);
    cudaFuncSetAttribute(attn_kernel, cudaFuncAttributeMaxDynamicSharedMemorySize, smem_bytes);
    attn_kernel<<<dim3(SEQ / BQ, NH), 256, smem_bytes>>>(qb, kvb, kpe, attn);
    // out = attn @ wo^T                     [2048 x 2048]
    gemm_nt<<<dim3(DIM / 128, SEQ / 128), blk>>>(attn, wo, out, SEQ, DIM, DIM, DIM, DIM, DIM);
}

// round 5
// speedup vs baseline: 1.3035x; 1.3035x over previous
#include <cuda_runtime.h>
#include <cuda_bf16.h>
#include <math.h>

#define SEQ   2048
#define DIM   2048
#define NH    16
#define QLR   768
#define KVLR  512
#define DN    128
#define DR    64
#define DV    128
#define QKH   192
#define HALF  96

#define SCALEF 0.0721687836487032f           // 192^-0.5
#define LAMBDA_INIT_F 0.556058204155754f     // 0.8 - 0.6*exp(-0.9)
#define ONE_MINUS_LI  0.443941795844246f

// ---------------- scratch (no allocations allowed) ----------------
__device__ float g_q[SEQ * NH * QKH];        // q (roped in place)
__device__ float g_kvfull[SEQ * (KVLR + DR)];
__device__ float g_kvb[SEQ * NH * (DN + DV)];
__device__ float g_kpe[SEQ * DR];
__device__ float g_attn[SEQ * NH * DV];
__device__ float g_lam;

// bf16 hi/lo operand buffers
__device__ __nv_bfloat16 g_xh[SEQ * DIM],     g_xl[SEQ * DIM];
__device__ __nv_bfloat16 g_qah[SEQ * QLR],    g_qal[SEQ * QLR];
__device__ __nv_bfloat16 g_kvfh[SEQ * (KVLR + DR)], g_kvfl[SEQ * (KVLR + DR)];
__device__ __nv_bfloat16 g_attnh[SEQ * NH * DV],    g_attnl[SEQ * NH * DV];
__device__ __nv_bfloat16 g_wqah[QLR * DIM],   g_wqal[QLR * DIM];
__device__ __nv_bfloat16 g_wqbh[NH * QKH * QLR], g_wqbl[NH * QKH * QLR];
__device__ __nv_bfloat16 g_wkvah[(KVLR + DR) * DIM], g_wkval[(KVLR + DR) * DIM];
__device__ __nv_bfloat16 g_wkvbh[NH * (DN + DV) * KVLR], g_wkvbl[NH * (DN + DV) * KVLR];
__device__ __nv_bfloat16 g_woh[DIM * NH * DV], g_wol[DIM * NH * DV];

// ---------------- helpers ----------------
__device__ __forceinline__ void mma16816(float* d, const unsigned* a, const unsigned* b) {
    asm volatile(
        "mma.sync.aligned.m16n8k16.row.col.f32.bf16.bf16.f32 "
        "{%0,%1,%2,%3},{%4,%5,%6,%7},{%8,%9},{%0,%1,%2,%3};\n"
        : "+f"(d[0]), "+f"(d[1]), "+f"(d[2]), "+f"(d[3])
        : "r"(a[0]), "r"(a[1]), "r"(a[2]), "r"(a[3]), "r"(b[0]), "r"(b[1]));
}

__device__ __forceinline__ void store_split2(__nv_bfloat16* H, __nv_bfloat16* L,
                                             size_t off, float x, float y) {
    __nv_bfloat16 hx = __float2bfloat16(x), hy = __float2bfloat16(y);
    float rx = x - __bfloat162float(hx), ry = y - __bfloat162float(hy);
    __nv_bfloat162 hv, lv;
    hv.x = hx; hv.y = hy;
    lv.x = __float2bfloat16(rx); lv.y = __float2bfloat16(ry);
    *(__nv_bfloat162*)&H[off] = hv;
    *(__nv_bfloat162*)&L[off] = lv;
}

// ---------------- fp32 -> bf16 hi/lo split ----------------
__global__ void split_kernel(const float* __restrict__ X,
                             __nv_bfloat16* __restrict__ H,
                             __nv_bfloat16* __restrict__ L, int n4) {
    int i = blockIdx.x * blockDim.x + threadIdx.x;
    if (i < n4) {
        float4 v = ((const float4*)X)[i];
        store_split2(H, L, (size_t)i * 4, v.x, v.y);
        store_split2(H, L, (size_t)i * 4 + 2, v.z, v.w);
    }
}

// ---------------- tensor-core GEMM: C[M,N] = A[M,K] @ B[N,K]^T ----------------
// bf16x3 fp32-emulation: C = Ah*Bh + Ah*Bl + Al*Bh, fp32 accum.
// 128x128 tile, BK=32, 256 threads (8 warps, 2m x 4n), warp tile 64x32.
__global__ __launch_bounds__(256) void gemm_bf16x3(
    const __nv_bfloat16* __restrict__ Ah, const __nv_bfloat16* __restrict__ Al,
    const __nv_bfloat16* __restrict__ Bh, const __nv_bfloat16* __restrict__ Bl,
    float* __restrict__ C, __nv_bfloat16* __restrict__ Ch, __nv_bfloat16* __restrict__ Cl,
    int M, int N, int K, int lda, int ldb, int ldc)
{
    __shared__ __align__(16) __nv_bfloat16 sAh[128 * 40];
    __shared__ __align__(16) __nv_bfloat16 sAl[128 * 40];
    __shared__ __align__(16) __nv_bfloat16 sBh[128 * 40];
    __shared__ __align__(16) __nv_bfloat16 sBl[128 * 40];

    const int tid  = threadIdx.x;
    const int m0   = blockIdx.y * 128;
    const int n0   = blockIdx.x * 128;
    const int lane = tid & 31;
    const int warp = tid >> 5;
    const int wm   = (warp >> 2) * 64;
    const int wn   = (warp & 3) * 32;
    const int grp  = lane >> 2;
    const int qp   = lane & 3;

    float acc[4][4][4];
#pragma unroll
    for (int f = 0; f < 4; f++)
#pragma unroll
        for (int g = 0; g < 4; g++)
#pragma unroll
            for (int e = 0; e < 4; e++) acc[f][g][e] = 0.f;

    for (int kt = 0; kt < K; kt += 32) {
#pragma unroll
        for (int i = 0; i < 4; i++) {
            const int c = tid + i * 256;
            const int row = c >> 3, kc = (c & 7) * 4;
            const size_t aoff = (size_t)(m0 + row) * lda + kt + kc;
            *(uint2*)&sAh[row * 40 + kc] = *(const uint2*)(Ah + aoff);
            *(uint2*)&sAl[row * 40 + kc] = *(const uint2*)(Al + aoff);
            uint2 vb = make_uint2(0u, 0u), vlb = make_uint2(0u, 0u);
            if (n0 + row < N) {
                const size_t boff = (size_t)(n0 + row) * ldb + kt + kc;
                vb  = *(const uint2*)(Bh + boff);
                vlb = *(const uint2*)(Bl + boff);
            }
            *(uint2*)&sBh[row * 40 + kc] = vb;
            *(uint2*)&sBl[row * 40 + kc] = vlb;
        }
        __syncthreads();

#pragma unroll
        for (int kk = 0; kk < 32; kk += 16) {
            unsigned ah[4][4], al[4][4], bh[4][2], bl[4][2];
#pragma unroll
            for (int f = 0; f < 4; f++) {
                const int r0 = (wm + f * 16 + grp) * 40 + kk + qp * 2;
                const int r1 = r0 + 8 * 40;
                ah[f][0] = *(const unsigned*)&sAh[r0];
                ah[f][1] = *(const unsigned*)&sAh[r1];
                ah[f][2] = *(const unsigned*)&sAh[r0 + 8];
                ah[f][3] = *(const unsigned*)&sAh[r1 + 8];
                al[f][0] = *(const unsigned*)&sAl[r0];
                al[f][1] = *(const unsigned*)&sAl[r1];
                al[f][2] = *(const unsigned*)&sAl[r0 + 8];
                al[f][3] = *(const unsigned*)&sAl[r1 + 8];
            }
#pragma unroll
            for (int g = 0; g < 4; g++) {
                const int nb = (wn + g * 8 + grp) * 40 + kk + qp * 2;
                bh[g][0] = *(const unsigned*)&sBh[nb];
                bh[g][1] = *(const unsigned*)&sBh[nb + 8];
                bl[g][0] = *(const unsigned*)&sBl[nb];
                bl[g][1] = *(const unsigned*)&sBl[nb + 8];
            }
#pragma unroll
            for (int f = 0; f < 4; f++)
#pragma unroll
                for (int g = 0; g < 4; g++) {
                    mma16816(acc[f][g], ah[f], bh[g]);
                    mma16816(acc[f][g], ah[f], bl[g]);
                    mma16816(acc[f][g], al[f], bh[g]);
                }
        }
        __syncthreads();
    }

#pragma unroll
    for (int f = 0; f < 4; f++)
#pragma unroll
        for (int g = 0; g < 4; g++) {
            const int r0  = m0 + wm + f * 16 + grp;
            const int col = n0 + wn + g * 8 + qp * 2;
            if (col < N) {
                const float* a = acc[f][g];
                if (C) {
                    *(float2*)&C[(size_t)r0 * ldc + col]       = make_float2(a[0], a[1]);
                    *(float2*)&C[(size_t)(r0 + 8) * ldc + col] = make_float2(a[2], a[3]);
                }
                if (Ch) {
                    store_split2(Ch, Cl, (size_t)r0 * ldc + col, a[0], a[1]);
                    store_split2(Ch, Cl, (size_t)(r0 + 8) * ldc + col, a[2], a[3]);
                }
            }
        }
}

// ---------------- RoPE (interleaved pairs) ----------------
__global__ void rope_kernel(float* __restrict__ q, const float* __restrict__ kvfull,
                            float* __restrict__ kpe,
                            const float* __restrict__ cosb, const float* __restrict__ sinb)
{
    const int s = blockIdx.x;
    for (int idx = threadIdx.x; idx < NH * 32 + 32; idx += blockDim.x) {
        if (idx < NH * 32) {
            const int h = idx >> 5, p = idx & 31;
            const float c = cosb[s * 32 + p], sn = sinb[s * 32 + p];
            float* base = q + (long)s * (NH * QKH) + h * QKH + DN;
            const float xr = base[2 * p], xi = base[2 * p + 1];
            base[2 * p]     = xr * c - xi * sn;
            base[2 * p + 1] = xr * sn + xi * c;
        } else {
            const int p = idx - NH * 32;
            const float c = cosb[s * 32 + p], sn = sinb[s * 32 + p];
            const float* kb = kvfull + (long)s * (KVLR + DR) + KVLR;
            const float xr = kb[2 * p], xi = kb[2 * p + 1];
            kpe[s * DR + 2 * p]     = xr * c - xi * sn;
            kpe[s * DR + 2 * p + 1] = xr * sn + xi * c;
        }
    }
}

// ---------------- lambda scalar ----------------
__global__ void lam_kernel(const float* __restrict__ lqn, const float* __restrict__ lqr,
                           const float* __restrict__ lkn, const float* __restrict__ lkr)
{
    if (threadIdx.x == 0) {
        float d1 = 0.f, d2 = 0.f;
        for (int i = 0; i < DN; i++) d1 += lqn[i] * lkn[i];
        for (int i = 0; i < DR; i++) d2 += lqr[i] * lkr[i];
        g_lam = expf(d1) - expf(d2) + LAMBDA_INIT_F;
    }
}

// ---------------- fused dual-softmax flash attention (unchanged from R2) ----------------
#define BQ 64
#define BK 32
#define QS_STRIDE 196
#define KS_STRIDE 33

#define SM_QS 0
#define SM_K1 (SM_QS + BQ * QS_STRIDE)
#define SM_K2 (SM_K1 + HALF * KS_STRIDE)
#define SM_VS (SM_K2 + HALF * KS_STRIDE)
#define SM_S1 (SM_VS + BK * DV)
#define SM_S2 (SM_S1 + BQ * KS_STRIDE)
#define SM_R1 (SM_S2 + BQ * KS_STRIDE)
#define SM_R2 (SM_R1 + BQ * 4)
#define SM_TOTAL (SM_R2 + BQ * 4)

__global__ __launch_bounds__(256, 2) void attn_kernel(
    const float* __restrict__ q, const float* __restrict__ kvb,
    const float* __restrict__ kpe, float* __restrict__ attn_out)
{
    extern __shared__ float sm[];
    float* Qs = sm + SM_QS;
    float* K1 = sm + SM_K1;
    float* K2 = sm + SM_K2;
    float* Vs = sm + SM_VS;
    float* S1 = sm + SM_S1;
    float* S2 = sm + SM_S2;
    float* R1 = sm + SM_R1;
    float* R2 = sm + SM_R2;

    const int tid = threadIdx.x;
    const int h = blockIdx.y;
    const int s0 = blockIdx.x * BQ;

    for (int idx = tid; idx < BQ * QKH; idx += 256) {
        const int r = idx / QKH, c = idx - r * QKH;
        Qs[r * QS_STRIDE + c] = q[(long)(s0 + r) * (NH * QKH) + h * QKH + c];
    }
    const float lam = g_lam;

    const int row = tid >> 2, quad = tid & 3;
    const int rg = tid >> 3, kg = tid & 7;

    float m1 = -1e30f, m2 = -1e30f, l1 = 0.f, l2 = 0.f;
    float o1[32], o2[32];
#pragma unroll
    for (int d = 0; d < 32; d++) { o1[d] = 0.f; o2[d] = 0.f; }

    __syncthreads();

    const int tend = s0 + BQ - 1;
    for (int t0 = 0; t0 <= tend; t0 += BK) {
        for (int idx = tid; idx < BK * 256; idx += 256) {
            const int tl = idx >> 8, c = idx & 255;
            const float v = kvb[(long)(t0 + tl) * (NH * 256) + h * 256 + c];
            if (c < HALF)       K1[c * KS_STRIDE + tl] = v;
            else if (c < DN)    K2[(c - HALF) * KS_STRIDE + tl] = v;
            else                Vs[tl * DV + (c - DN)] = v;
        }
        for (int idx = tid; idx < BK * DR; idx += 256) {
            const int tl = idx >> 6, c = idx & 63;
            K2[(32 + c) * KS_STRIDE + tl] = kpe[(t0 + tl) * DR + c];
        }
        __syncthreads();

        {
            float a1[2][4], a2[2][4];
#pragma unroll
            for (int i = 0; i < 2; i++)
#pragma unroll
                for (int j = 0; j < 4; j++) { a1[i][j] = 0.f; a2[i][j] = 0.f; }
            const float* q0 = &Qs[(rg * 2) * QS_STRIDE];
            const float* q1 = &Qs[(rg * 2 + 1) * QS_STRIDE];
#pragma unroll 4
            for (int c = 0; c < HALF; c++) {
                const float qa = q0[c], qb = q1[c];
                const float qa2 = q0[HALF + c], qb2 = q1[HALF + c];
#pragma unroll
                for (int j = 0; j < 4; j++) {
                    const float k1v = K1[c * KS_STRIDE + kg * 4 + j];
                    const float k2v = K2[c * KS_STRIDE + kg * 4 + j];
                    a1[0][j] += qa * k1v;  a1[1][j] += qb * k1v;
                    a2[0][j] += qa2 * k2v; a2[1][j] += qb2 * k2v;
                }
            }
#pragma unroll
            for (int i = 0; i < 2; i++) {
                const int r = rg * 2 + i;
#pragma unroll
                for (int j = 0; j < 4; j++) {
                    const int k = kg * 4 + j;
                    float v1 = fminf(fmaxf(a1[i][j] * SCALEF, -100.f), 100.f);
                    float v2 = fminf(fmaxf(a2[i][j] * SCALEF, -100.f), 100.f);
                    if (t0 + k > s0 + r) { v1 = -1e9f; v2 = -1e9f; }
                    S1[r * KS_STRIDE + k] = v1;
                    S2[r * KS_STRIDE + k] = v2;
                }
            }
        }
        __syncthreads();

        float pm1 = -1e30f, pm2 = -1e30f;
#pragma unroll
        for (int j = 0; j < 8; j++) {
            const int k = quad * 8 + j;
            pm1 = fmaxf(pm1, S1[row * KS_STRIDE + k]);
            pm2 = fmaxf(pm2, S2[row * KS_STRIDE + k]);
        }
        R1[row * 4 + quad] = pm1;
        R2[row * 4 + quad] = pm2;
        __syncthreads();

        float m1n = m1, m2n = m2;
#pragma unroll
        for (int j = 0; j < 4; j++) {
            m1n = fmaxf(m1n, R1[row * 4 + j]);
            m2n = fmaxf(m2n, R2[row * 4 + j]);
        }

        float ps1 = 0.f, ps2 = 0.f;
#pragma unroll
        for (int j = 0; j < 8; j++) {
            const int k = quad * 8 + j;
            const float p1 = __expf(S1[row * KS_STRIDE + k] - m1n);
            const float p2 = __expf(S2[row * KS_STRIDE + k] - m2n);
            S1[row * KS_STRIDE + k] = p1;
            S2[row * KS_STRIDE + k] = p2;
            ps1 += p1; ps2 += p2;
        }
        __syncthreads();
        R1[row * 4 + quad] = ps1;
        R2[row * 4 + quad] = ps2;
        __syncthreads();

        float ts1 = 0.f, ts2 = 0.f;
#pragma unroll
        for (int j = 0; j < 4; j++) { ts1 += R1[row * 4 + j]; ts2 += R2[row * 4 + j]; }
        const float sc1 = __expf(m1 - m1n);
        const float sc2 = __expf(m2 - m2n);
        l1 = l1 * sc1 + ts1;
        l2 = l2 * sc2 + ts2;
        m1 = m1n; m2 = m2n;

#pragma unroll
        for (int d = 0; d < 32; d++) { o1[d] *= sc1; o2[d] *= sc2; }

#pragma unroll 4
        for (int k = 0; k < BK; k++) {
            const float p1 = S1[row * KS_STRIDE + k];
            const float p2 = S2[row * KS_STRIDE + k];
#pragma unroll
            for (int d = 0; d < 32; d++) {
                const float v = Vs[k * DV + quad + 4 * d];
                o1[d] += p1 * v;
                o2[d] += p2 * v;
            }
        }
        __syncthreads();
    }

    const float i1 = 1.f / l1;
    const float i2 = lam / l2;
    float* outp = &attn_out[(long)(s0 + row) * (NH * DV) + h * DV + quad];
#pragma unroll
    for (int d = 0; d < 32; d++)
        outp[4 * d] = (o1[d] * i1 - o2[d] * i2) * ONE_MINUS_LI;
}

// ---------------- launch ----------------
static inline void launch_split(const float* X, __nv_bfloat16* H, __nv_bfloat16* L, int n) {
    const int n4 = n / 4;
    split_kernel<<<(n4 + 255) / 256, 256>>>(X, H, L, n4);
}

extern "C" void kernel_launch(void* const* d_in, const int* in_sizes, int n_in,
                              void* d_out, int out_size)
{
    const float* x     = (const float*)d_in[0];
    const float* wq_a  = (const float*)d_in[1];
    const float* wq_b  = (const float*)d_in[2];
    const float* wkv_a = (const float*)d_in[3];
    const float* wkv_b = (const float*)d_in[4];
    const float* wo    = (const float*)d_in[5];
    const float* lqn   = (const float*)d_in[6];
    const float* lqr   = (const float*)d_in[7];
    const float* lkn   = (const float*)d_in[8];
    const float* lkr   = (const float*)d_in[9];
    const float* fcos  = (const float*)d_in[10];
    const float* fsin  = (const float*)d_in[11];
    float* out = (float*)d_out;

    float *qb, *kvf, *kvb, *kpe, *attn;
    cudaGetSymbolAddress((void**)&qb,   g_q);
    cudaGetSymbolAddress((void**)&kvf,  g_kvfull);
    cudaGetSymbolAddress((void**)&kvb,  g_kvb);
    cudaGetSymbolAddress((void**)&kpe,  g_kpe);
    cudaGetSymbolAddress((void**)&attn, g_attn);

    __nv_bfloat16 *xh,*xl,*qah,*qal,*kvfh,*kvfl,*attnh,*attnl;
    __nv_bfloat16 *wqah,*wqal,*wqbh,*wqbl,*wkvah,*wkval,*wkvbh,*wkvbl,*woh,*wol;
    cudaGetSymbolAddress((void**)&xh, g_xh);     cudaGetSymbolAddress((void**)&xl, g_xl);
    cudaGetSymbolAddress((void**)&qah, g_qah);   cudaGetSymbolAddress((void**)&qal, g_qal);
    cudaGetSymbolAddress((void**)&kvfh, g_kvfh); cudaGetSymbolAddress((void**)&kvfl, g_kvfl);
    cudaGetSymbolAddress((void**)&attnh, g_attnh); cudaGetSymbolAddress((void**)&attnl, g_attnl);
    cudaGetSymbolAddress((void**)&wqah, g_wqah); cudaGetSymbolAddress((void**)&wqal, g_wqal);
    cudaGetSymbolAddress((void**)&wqbh, g_wqbh); cudaGetSymbolAddress((void**)&wqbl, g_wqbl);
    cudaGetSymbolAddress((void**)&wkvah, g_wkvah); cudaGetSymbolAddress((void**)&wkval, g_wkval);
    cudaGetSymbolAddress((void**)&wkvbh, g_wkvbh); cudaGetSymbolAddress((void**)&wkvbl, g_wkvbl);
    cudaGetSymbolAddress((void**)&woh, g_woh);   cudaGetSymbolAddress((void**)&wol, g_wol);

    // splits of inputs
    launch_split(x,     xh,    xl,    SEQ * DIM);
    launch_split(wq_a,  wqah,  wqal,  QLR * DIM);
    launch_split(wq_b,  wqbh,  wqbl,  NH * QKH * QLR);
    launch_split(wkv_a, wkvah, wkval, (KVLR + DR) * DIM);
    launch_split(wkv_b, wkvbh, wkvbl, NH * (DN + DV) * KVLR);
    launch_split(wo,    woh,   wol,   DIM * NH * DV);

    const dim3 blk(256);

    // qa = x @ wq_a^T  -> bf16 hi/lo only
    gemm_bf16x3<<<dim3(QLR / 128, SEQ / 128), blk>>>(
        xh, xl, wqah, wqal, nullptr, qah, qal, SEQ, QLR, DIM, DIM, DIM, QLR);
    // q = qa @ wq_b^T  -> fp32
    gemm_bf16x3<<<dim3((NH * QKH) / 128, SEQ / 128), blk>>>(
        qah, qal, wqbh, wqbl, qb, nullptr, nullptr, SEQ, NH * QKH, QLR, QLR, QLR, NH * QKH);
    // kv_full = x @ wkv_a^T -> fp32 + hi/lo
    gemm_bf16x3<<<dim3((KVLR + DR + 127) / 128, SEQ / 128), blk>>>(
        xh, xl, wkvah, wkval, kvf, kvfh, kvfl, SEQ, KVLR + DR, DIM, DIM, DIM, KVLR + DR);
    // RoPE
    rope_kernel<<<SEQ, 256>>>(qb, kvf, kpe, fcos, fsin);
    // kvb = kv_full[:, :512] @ wkv_b^T -> fp32
    gemm_bf16x3<<<dim3((NH * (DN + DV)) / 128, SEQ / 128), blk>>>(
        kvfh, kvfl, wkvbh, wkvbl, kvb, nullptr, nullptr,
        SEQ, NH * (DN + DV), KVLR, KVLR + DR, KVLR, NH * (DN + DV));
    // lambda
    lam_kernel<<<1, 32>>>(lqn, lqr, lkn, lkr);
    // attention (fp32)
    const int smem_bytes = SM_TOTAL * (int)sizeof(float);
    cudaFuncSetAttribute(attn_kernel, cudaFuncAttributeMaxDynamicSharedMemorySize, smem_bytes);
    attn_kernel<<<dim3(SEQ / BQ, NH), 256, smem_bytes>>>(qb, kvb, kpe, attn);
    // split attention output
    launch_split(attn, attnh, attnl, SEQ * NH * DV);
    // out = attn @ wo^T -> fp32 (d_out)
    gemm_bf16x3<<<dim3(DIM / 128, SEQ / 128), blk>>>(
        attnh, attnl, woh, wol, out, nullptr, nullptr, SEQ, DIM, DIM, DIM, DIM, DIM);
}

// round 7
// speedup vs baseline: 2.3182x; 1.7784x over previous
#include <cuda_runtime.h>
#include <cuda_bf16.h>
#include <math.h>

#define SEQ   2048
#define DIM   2048
#define NH    16
#define QLR   768
#define KVLR  512
#define DN    128
#define DR    64
#define DV    128
#define QKH   192
#define HALF  96

#define SCALEF 0.0721687836487032f           // 192^-0.5
#define LAMBDA_INIT_F 0.556058204155754f     // 0.8 - 0.6*exp(-0.9)
#define ONE_MINUS_LI  0.443941795844246f

// ---------------- scratch (no allocations allowed) ----------------
__device__ float g_q[SEQ * NH * QKH];        // q (roped in place)
__device__ float g_kvfull[SEQ * (KVLR + DR)];
__device__ float g_kvb[SEQ * NH * (DN + DV)];
__device__ float g_kpe[SEQ * DR];
__device__ float g_lam;

// bf16 hi/lo operand buffers
__device__ __nv_bfloat16 g_xh[SEQ * DIM],     g_xl[SEQ * DIM];
__device__ __nv_bfloat16 g_qah[SEQ * QLR],    g_qal[SEQ * QLR];
__device__ __nv_bfloat16 g_kvfh[SEQ * (KVLR + DR)], g_kvfl[SEQ * (KVLR + DR)];
__device__ __nv_bfloat16 g_attnh[SEQ * NH * DV],    g_attnl[SEQ * NH * DV];
__device__ __nv_bfloat16 g_wqah[QLR * DIM],   g_wqal[QLR * DIM];
__device__ __nv_bfloat16 g_wqbh[NH * QKH * QLR], g_wqbl[NH * QKH * QLR];
__device__ __nv_bfloat16 g_wkvah[(KVLR + DR) * DIM], g_wkval[(KVLR + DR) * DIM];
__device__ __nv_bfloat16 g_wkvbh[NH * (DN + DV) * KVLR], g_wkvbl[NH * (DN + DV) * KVLR];
__device__ __nv_bfloat16 g_woh[DIM * NH * DV], g_wol[DIM * NH * DV];

// ---------------- helpers ----------------
__device__ __forceinline__ void mma16816(float* d, const unsigned* a, const unsigned* b) {
    asm volatile(
        "mma.sync.aligned.m16n8k16.row.col.f32.bf16.bf16.f32 "
        "{%0,%1,%2,%3},{%4,%5,%6,%7},{%8,%9},{%0,%1,%2,%3};\n"
        : "+f"(d[0]), "+f"(d[1]), "+f"(d[2]), "+f"(d[3])
        : "r"(a[0]), "r"(a[1]), "r"(a[2]), "r"(a[3]), "r"(b[0]), "r"(b[1]));
}

__device__ __forceinline__ void store_split2(__nv_bfloat16* H, __nv_bfloat16* L,
                                             size_t off, float x, float y) {
    __nv_bfloat16 hx = __float2bfloat16(x), hy = __float2bfloat16(y);
    float rx = x - __bfloat162float(hx), ry = y - __bfloat162float(hy);
    __nv_bfloat162 hv, lv;
    hv.x = hx; hv.y = hy;
    lv.x = __float2bfloat16(rx); lv.y = __float2bfloat16(ry);
    *(__nv_bfloat162*)&H[off] = hv;
    *(__nv_bfloat162*)&L[off] = lv;
}

__device__ __forceinline__ unsigned packbf(float a, float b) {
    __nv_bfloat162 t = __floats2bfloat162_rn(a, b);
    return *(unsigned*)&t;
}

// pack hi and residual-lo bf16x2 fragments from two fp32 values
__device__ __forceinline__ void packsplit(float a, float b, unsigned& h, unsigned& l) {
    __nv_bfloat16 ha = __float2bfloat16(a), hb = __float2bfloat16(b);
    __nv_bfloat162 hv; hv.x = ha; hv.y = hb;
    h = *(unsigned*)&hv;
    l = packbf(a - __bfloat162float(ha), b - __bfloat162float(hb));
}

// ---------------- fp32 -> bf16 hi/lo split ----------------
__global__ void split_kernel(const float* __restrict__ X,
                             __nv_bfloat16* __restrict__ H,
                             __nv_bfloat16* __restrict__ L, int n4) {
    int i = blockIdx.x * blockDim.x + threadIdx.x;
    if (i < n4) {
        float4 v = ((const float4*)X)[i];
        store_split2(H, L, (size_t)i * 4, v.x, v.y);
        store_split2(H, L, (size_t)i * 4 + 2, v.z, v.w);
    }
}

// ---------------- tensor-core GEMM: C[M,N] = A[M,K] @ B[N,K]^T (unchanged) ----------------
__global__ __launch_bounds__(256) void gemm_bf16x3(
    const __nv_bfloat16* __restrict__ Ah, const __nv_bfloat16* __restrict__ Al,
    const __nv_bfloat16* __restrict__ Bh, const __nv_bfloat16* __restrict__ Bl,
    float* __restrict__ C, __nv_bfloat16* __restrict__ Ch, __nv_bfloat16* __restrict__ Cl,
    int M, int N, int K, int lda, int ldb, int ldc)
{
    __shared__ __align__(16) __nv_bfloat16 sAh[128 * 40];
    __shared__ __align__(16) __nv_bfloat16 sAl[128 * 40];
    __shared__ __align__(16) __nv_bfloat16 sBh[128 * 40];
    __shared__ __align__(16) __nv_bfloat16 sBl[128 * 40];

    const int tid  = threadIdx.x;
    const int m0   = blockIdx.y * 128;
    const int n0   = blockIdx.x * 128;
    const int lane = tid & 31;
    const int warp = tid >> 5;
    const int wm   = (warp >> 2) * 64;
    const int wn   = (warp & 3) * 32;
    const int grp  = lane >> 2;
    const int qp   = lane & 3;

    float acc[4][4][4];
#pragma unroll
    for (int f = 0; f < 4; f++)
#pragma unroll
        for (int g = 0; g < 4; g++)
#pragma unroll
            for (int e = 0; e < 4; e++) acc[f][g][e] = 0.f;

    for (int kt = 0; kt < K; kt += 32) {
#pragma unroll
        for (int i = 0; i < 4; i++) {
            const int c = tid + i * 256;
            const int row = c >> 3, kc = (c & 7) * 4;
            const size_t aoff = (size_t)(m0 + row) * lda + kt + kc;
            *(uint2*)&sAh[row * 40 + kc] = *(const uint2*)(Ah + aoff);
            *(uint2*)&sAl[row * 40 + kc] = *(const uint2*)(Al + aoff);
            uint2 vb = make_uint2(0u, 0u), vlb = make_uint2(0u, 0u);
            if (n0 + row < N) {
                const size_t boff = (size_t)(n0 + row) * ldb + kt + kc;
                vb  = *(const uint2*)(Bh + boff);
                vlb = *(const uint2*)(Bl + boff);
            }
            *(uint2*)&sBh[row * 40 + kc] = vb;
            *(uint2*)&sBl[row * 40 + kc] = vlb;
        }
        __syncthreads();

#pragma unroll
        for (int kk = 0; kk < 32; kk += 16) {
            unsigned ah[4][4], al[4][4], bh[4][2], bl[4][2];
#pragma unroll
            for (int f = 0; f < 4; f++) {
                const int r0 = (wm + f * 16 + grp) * 40 + kk + qp * 2;
                const int r1 = r0 + 8 * 40;
                ah[f][0] = *(const unsigned*)&sAh[r0];
                ah[f][1] = *(const unsigned*)&sAh[r1];
                ah[f][2] = *(const unsigned*)&sAh[r0 + 8];
                ah[f][3] = *(const unsigned*)&sAh[r1 + 8];
                al[f][0] = *(const unsigned*)&sAl[r0];
                al[f][1] = *(const unsigned*)&sAl[r1];
                al[f][2] = *(const unsigned*)&sAl[r0 + 8];
                al[f][3] = *(const unsigned*)&sAl[r1 + 8];
            }
#pragma unroll
            for (int g = 0; g < 4; g++) {
                const int nb = (wn + g * 8 + grp) * 40 + kk + qp * 2;
                bh[g][0] = *(const unsigned*)&sBh[nb];
                bh[g][1] = *(const unsigned*)&sBh[nb + 8];
                bl[g][0] = *(const unsigned*)&sBl[nb];
                bl[g][1] = *(const unsigned*)&sBl[nb + 8];
            }
#pragma unroll
            for (int f = 0; f < 4; f++)
#pragma unroll
                for (int g = 0; g < 4; g++) {
                    mma16816(acc[f][g], ah[f], bh[g]);
                    mma16816(acc[f][g], ah[f], bl[g]);
                    mma16816(acc[f][g], al[f], bh[g]);
                }
        }
        __syncthreads();
    }

#pragma unroll
    for (int f = 0; f < 4; f++)
#pragma unroll
        for (int g = 0; g < 4; g++) {
            const int r0  = m0 + wm + f * 16 + grp;
            const int col = n0 + wn + g * 8 + qp * 2;
            if (col < N) {
                const float* a = acc[f][g];
                if (C) {
                    *(float2*)&C[(size_t)r0 * ldc + col]       = make_float2(a[0], a[1]);
                    *(float2*)&C[(size_t)(r0 + 8) * ldc + col] = make_float2(a[2], a[3]);
                }
                if (Ch) {
                    store_split2(Ch, Cl, (size_t)r0 * ldc + col, a[0], a[1]);
                    store_split2(Ch, Cl, (size_t)(r0 + 8) * ldc + col, a[2], a[3]);
                }
            }
        }
}

// ---------------- RoPE (interleaved pairs) ----------------
__global__ void rope_kernel(float* __restrict__ q, const float* __restrict__ kvfull,
                            float* __restrict__ kpe,
                            const float* __restrict__ cosb, const float* __restrict__ sinb)
{
    const int s = blockIdx.x;
    for (int idx = threadIdx.x; idx < NH * 32 + 32; idx += blockDim.x) {
        if (idx < NH * 32) {
            const int h = idx >> 5, p = idx & 31;
            const float c = cosb[s * 32 + p], sn = sinb[s * 32 + p];
            float* base = q + (long)s * (NH * QKH) + h * QKH + DN;
            const float xr = base[2 * p], xi = base[2 * p + 1];
            base[2 * p]     = xr * c - xi * sn;
            base[2 * p + 1] = xr * sn + xi * c;
        } else {
            const int p = idx - NH * 32;
            const float c = cosb[s * 32 + p], sn = sinb[s * 32 + p];
            const float* kb = kvfull + (long)s * (KVLR + DR) + KVLR;
            const float xr = kb[2 * p], xi = kb[2 * p + 1];
            kpe[s * DR + 2 * p]     = xr * c - xi * sn;
            kpe[s * DR + 2 * p + 1] = xr * sn + xi * c;
        }
    }
}

// ---------------- lambda scalar ----------------
__global__ void lam_kernel(const float* __restrict__ lqn, const float* __restrict__ lqr,
                           const float* __restrict__ lkn, const float* __restrict__ lkr)
{
    if (threadIdx.x == 0) {
        float d1 = 0.f, d2 = 0.f;
        for (int i = 0; i < DN; i++) d1 += lqn[i] * lkn[i];
        for (int i = 0; i < DR; i++) d2 += lqr[i] * lkr[i];
        g_lam = expf(d1) - expf(d2) + LAMBDA_INIT_F;
    }
}

// ---------------- tensor-core dual-softmax flash attention ----------------
// BQ=128 rows/block-half, BK=64 keys/tile. 8 warps; warp w owns rows [16w,16w+16).
// Each block processes q-tile qi=blockIdx.x and 15-blockIdx.x (constant total work).
// P and V both kept as bf16 hi/lo; P@V is 3-term (error O(eps^2)).
#define ABQ 128
#define ABK 64
#define KSTR 200
#define VSTR 72
#define ASMEM_ELEMS (2*ABQ*KSTR + 2*ABK*KSTR + 2*DV*VSTR)

__global__ __launch_bounds__(256, 1) void attn_mma_kernel(
    const float* __restrict__ q, const float* __restrict__ kvb,
    const float* __restrict__ kpe,
    __nv_bfloat16* __restrict__ outh, __nv_bfloat16* __restrict__ outl,
    const float* __restrict__ lamp)
{
    extern __shared__ __nv_bfloat16 sb[];
    __nv_bfloat16* Qh  = sb;
    __nv_bfloat16* Ql  = Qh  + ABQ * KSTR;
    __nv_bfloat16* Kh  = Ql  + ABQ * KSTR;
    __nv_bfloat16* Kl  = Kh  + ABK * KSTR;
    __nv_bfloat16* VTh = Kl  + ABK * KSTR;   // [DV][VSTR] transposed V hi
    __nv_bfloat16* VTl = VTh + DV * VSTR;    // [DV][VSTR] transposed V lo

    const int tid  = threadIdx.x;
    const int lane = tid & 31;
    const int warp = tid >> 5;
    const int grp  = lane >> 2;
    const int tig  = lane & 3;
    const int wm   = warp * 16;
    const int h    = blockIdx.y;
    const float lam = *lamp;

    for (int half = 0; half < 2; half++) {
        const int qi = (half == 0) ? (int)blockIdx.x : (15 - (int)blockIdx.x);
        const int s0 = qi * ABQ;

        __syncthreads();   // previous half's compute fully done before smem rewrite

        // ---- load Q tile (fp32 -> hi/lo bf16): thread row=tid>>1, 96 dims ----
        {
            const int r  = tid >> 1;
            const int d0 = (tid & 1) * 96;
            const float* src = q + (size_t)(s0 + r) * (NH * QKH) + h * QKH + d0;
#pragma unroll
            for (int d = 0; d < 96; d += 2)
                store_split2(Qh, Ql, (size_t)r * KSTR + d0 + d, src[d], src[d + 1]);
        }

        float o1[16][4], o2[16][4];
#pragma unroll
        for (int v = 0; v < 16; v++)
#pragma unroll
            for (int e = 0; e < 4; e++) { o1[v][e] = 0.f; o2[v][e] = 0.f; }
        float m_[2][2] = {{-1e30f, -1e30f}, {-1e30f, -1e30f}};
        float l_[2][2] = {{0.f, 0.f}, {0.f, 0.f}};

        const int ntiles = s0 / ABK + 2;
        for (int tix = 0; tix < ntiles; tix++) {
            const int t0 = tix * ABK;
            if (tix > 0) __syncthreads();   // compute done before K/V rewrite
            // ---- load K tile (192 dims -> hi/lo) and V^T (hi/lo bf16) ----
            {
                const int k  = tid >> 2;
                const int d0 = (tid & 3) * 48;
                const float* kn = kvb + (size_t)(t0 + k) * (NH * 256) + h * 256;
                const float* kp = kpe + (size_t)(t0 + k) * DR;
#pragma unroll
                for (int i = 0; i < 48; i += 2) {
                    const int d = d0 + i;
                    const float a = (d < 128)     ? kn[d]     : kp[d - 128];
                    const float b = (d + 1 < 128) ? kn[d + 1] : kp[d - 127];
                    store_split2(Kh, Kl, (size_t)k * KSTR + d, a, b);
                }
                const int vd0 = (tid & 3) * 32;
#pragma unroll
                for (int i = 0; i < 32; i++) {
                    const float val = kn[128 + vd0 + i];
                    const __nv_bfloat16 hv = __float2bfloat16(val);
                    VTh[(vd0 + i) * VSTR + k] = hv;
                    VTl[(vd0 + i) * VSTR + k] =
                        __float2bfloat16(val - __bfloat162float(hv));
                }
            }
            __syncthreads();

            if (t0 <= s0 + wm + 15) {       // warp-uniform skip of fully-masked tiles
#pragma unroll
                for (int br = 0; br < 2; br++) {
                    const int kb = br * HALF;
                    float acc[8][4];
#pragma unroll
                    for (int j = 0; j < 8; j++)
#pragma unroll
                        for (int e = 0; e < 4; e++) acc[j][e] = 0.f;

#pragma unroll
                    for (int t = 0; t < 6; t++) {
                        const int kk = kb + t * 16;
                        unsigned ah[4], al[4];
                        const int qo = (wm + grp) * KSTR + kk + 2 * tig;
                        ah[0] = *(const unsigned*)&Qh[qo];
                        ah[1] = *(const unsigned*)&Qh[qo + 8 * KSTR];
                        ah[2] = *(const unsigned*)&Qh[qo + 8];
                        ah[3] = *(const unsigned*)&Qh[qo + 8 * KSTR + 8];
                        al[0] = *(const unsigned*)&Ql[qo];
                        al[1] = *(const unsigned*)&Ql[qo + 8 * KSTR];
                        al[2] = *(const unsigned*)&Ql[qo + 8];
                        al[3] = *(const unsigned*)&Ql[qo + 8 * KSTR + 8];
#pragma unroll
                        for (int j = 0; j < 8; j++) {
                            unsigned bh[2], bl[2];
                            const int ko = (8 * j + grp) * KSTR + kk + 2 * tig;
                            bh[0] = *(const unsigned*)&Kh[ko];
                            bh[1] = *(const unsigned*)&Kh[ko + 8];
                            bl[0] = *(const unsigned*)&Kl[ko];
                            bl[1] = *(const unsigned*)&Kl[ko + 8];
                            mma16816(acc[j], ah, bh);
                            mma16816(acc[j], ah, bl);
                            mma16816(acc[j], al, bh);
                        }
                    }

                    // clip + causal mask
                    const int r0 = s0 + wm + grp, r1 = r0 + 8;
#pragma unroll
                    for (int j = 0; j < 8; j++)
#pragma unroll
                        for (int e = 0; e < 4; e++) {
                            const int key = t0 + 8 * j + 2 * tig + (e & 1);
                            const int row = (e < 2) ? r0 : r1;
                            float v = fminf(fmaxf(acc[j][e] * SCALEF, -100.f), 100.f);
                            acc[j][e] = (key > row) ? -1e9f : v;
                        }

                    // row max across 64 keys (quad shuffle)
                    float mx0 = -1e30f, mx1 = -1e30f;
#pragma unroll
                    for (int j = 0; j < 8; j++) {
                        mx0 = fmaxf(mx0, fmaxf(acc[j][0], acc[j][1]));
                        mx1 = fmaxf(mx1, fmaxf(acc[j][2], acc[j][3]));
                    }
                    mx0 = fmaxf(mx0, __shfl_xor_sync(0xffffffffu, mx0, 1));
                    mx0 = fmaxf(mx0, __shfl_xor_sync(0xffffffffu, mx0, 2));
                    mx1 = fmaxf(mx1, __shfl_xor_sync(0xffffffffu, mx1, 1));
                    mx1 = fmaxf(mx1, __shfl_xor_sync(0xffffffffu, mx1, 2));

                    const float mo0 = m_[br][0], mo1 = m_[br][1];
                    const float mn0 = fmaxf(mo0, mx0), mn1 = fmaxf(mo1, mx1);
                    const float sc0 = __expf(mo0 - mn0), sc1 = __expf(mo1 - mn1);
                    m_[br][0] = mn0; m_[br][1] = mn1;

                    float su0 = 0.f, su1 = 0.f;
#pragma unroll
                    for (int j = 0; j < 8; j++) {
                        float p0 = __expf(acc[j][0] - mn0);
                        float p1 = __expf(acc[j][1] - mn0);
                        float p2 = __expf(acc[j][2] - mn1);
                        float p3 = __expf(acc[j][3] - mn1);
                        acc[j][0] = p0; acc[j][1] = p1; acc[j][2] = p2; acc[j][3] = p3;
                        su0 += p0 + p1; su1 += p2 + p3;
                    }
                    su0 += __shfl_xor_sync(0xffffffffu, su0, 1);
                    su0 += __shfl_xor_sync(0xffffffffu, su0, 2);
                    su1 += __shfl_xor_sync(0xffffffffu, su1, 1);
                    su1 += __shfl_xor_sync(0xffffffffu, su1, 2);
                    l_[br][0] = l_[br][0] * sc0 + su0;
                    l_[br][1] = l_[br][1] * sc1 + su1;

                    // rescale O for this branch
                    float (*ob)[4] = br ? o2 : o1;
#pragma unroll
                    for (int v = 0; v < 16; v++) {
                        ob[v][0] *= sc0; ob[v][1] *= sc0;
                        ob[v][2] *= sc1; ob[v][3] *= sc1;
                    }

                    // pack P -> hi/lo A fragments (C layout == A layout identity)
                    unsigned pa[4][4], pal[4][4];
#pragma unroll
                    for (int t = 0; t < 4; t++) {
                        packsplit(acc[2 * t][0],     acc[2 * t][1],     pa[t][0], pal[t][0]);
                        packsplit(acc[2 * t][2],     acc[2 * t][3],     pa[t][1], pal[t][1]);
                        packsplit(acc[2 * t + 1][0], acc[2 * t + 1][1], pa[t][2], pal[t][2]);
                        packsplit(acc[2 * t + 1][2], acc[2 * t + 1][3], pa[t][3], pal[t][3]);
                    }

                    // P@V 3-term for this branch: Ph*Vh + Pl*Vh + Ph*Vl
#pragma unroll
                    for (int v = 0; v < 16; v++) {
#pragma unroll
                        for (int t = 0; t < 4; t++) {
                            unsigned bvh[2], bvl[2];
                            const int vo = (8 * v + grp) * VSTR + 16 * t + 2 * tig;
                            bvh[0] = *(const unsigned*)&VTh[vo];
                            bvh[1] = *(const unsigned*)&VTh[vo + 8];
                            bvl[0] = *(const unsigned*)&VTl[vo];
                            bvl[1] = *(const unsigned*)&VTl[vo + 8];
                            mma16816(ob[v], pa[t],  bvh);
                            mma16816(ob[v], pal[t], bvh);
                            mma16816(ob[v], pa[t],  bvl);
                        }
                    }
                }
            }
        }

        // ---- epilogue: combine branches, write hi/lo split directly ----
        const float i10 = 1.f / l_[0][0], i11 = 1.f / l_[0][1];
        const float i20 = lam / l_[1][0], i21 = lam / l_[1][1];
        const int r0 = s0 + wm + grp, r1 = r0 + 8;
#pragma unroll
        for (int v = 0; v < 16; v++) {
            const int col = h * DV + 8 * v + 2 * tig;
            const float a0 = (o1[v][0] * i10 - o2[v][0] * i20) * ONE_MINUS_LI;
            const float a1 = (o1[v][1] * i10 - o2[v][1] * i20) * ONE_MINUS_LI;
            const float a2 = (o1[v][2] * i11 - o2[v][2] * i21) * ONE_MINUS_LI;
            const float a3 = (o1[v][3] * i11 - o2[v][3] * i21) * ONE_MINUS_LI;
            store_split2(outh, outl, (size_t)r0 * (NH * DV) + col, a0, a1);
            store_split2(outh, outl, (size_t)r1 * (NH * DV) + col, a2, a3);
        }
    }
}

// ---------------- launch ----------------
static inline void launch_split(const float* X, __nv_bfloat16* H, __nv_bfloat16* L, int n) {
    const int n4 = n / 4;
    split_kernel<<<(n4 + 255) / 256, 256>>>(X, H, L, n4);
}

extern "C" void kernel_launch(void* const* d_in, const int* in_sizes, int n_in,
                              void* d_out, int out_size)
{
    const float* x     = (const float*)d_in[0];
    const float* wq_a  = (const float*)d_in[1];
    const float* wq_b  = (const float*)d_in[2];
    const float* wkv_a = (const float*)d_in[3];
    const float* wkv_b = (const float*)d_in[4];
    const float* wo    = (const float*)d_in[5];
    const float* lqn   = (const float*)d_in[6];
    const float* lqr   = (const float*)d_in[7];
    const float* lkn   = (const float*)d_in[8];
    const float* lkr   = (const float*)d_in[9];
    const float* fcos  = (const float*)d_in[10];
    const float* fsin  = (const float*)d_in[11];
    float* out = (float*)d_out;

    float *qb, *kvf, *kvb, *kpe, *lamp;
    cudaGetSymbolAddress((void**)&qb,   g_q);
    cudaGetSymbolAddress((void**)&kvf,  g_kvfull);
    cudaGetSymbolAddress((void**)&kvb,  g_kvb);
    cudaGetSymbolAddress((void**)&kpe,  g_kpe);
    cudaGetSymbolAddress((void**)&lamp, g_lam);

    __nv_bfloat16 *xh,*xl,*qah,*qal,*kvfh,*kvfl,*attnh,*attnl;
    __nv_bfloat16 *wqah,*wqal,*wqbh,*wqbl,*wkvah,*wkval,*wkvbh,*wkvbl,*woh,*wol;
    cudaGetSymbolAddress((void**)&xh, g_xh);     cudaGetSymbolAddress((void**)&xl, g_xl);
    cudaGetSymbolAddress((void**)&qah, g_qah);   cudaGetSymbolAddress((void**)&qal, g_qal);
    cudaGetSymbolAddress((void**)&kvfh, g_kvfh); cudaGetSymbolAddress((void**)&kvfl, g_kvfl);
    cudaGetSymbolAddress((void**)&attnh, g_attnh); cudaGetSymbolAddress((void**)&attnl, g_attnl);
    cudaGetSymbolAddress((void**)&wqah, g_wqah); cudaGetSymbolAddress((void**)&wqal, g_wqal);
    cudaGetSymbolAddress((void**)&wqbh, g_wqbh); cudaGetSymbolAddress((void**)&wqbl, g_wqbl);
    cudaGetSymbolAddress((void**)&wkvah, g_wkvah); cudaGetSymbolAddress((void**)&wkval, g_wkval);
    cudaGetSymbolAddress((void**)&wkvbh, g_wkvbh); cudaGetSymbolAddress((void**)&wkvbl, g_wkvbl);
    cudaGetSymbolAddress((void**)&woh, g_woh);   cudaGetSymbolAddress((void**)&wol, g_wol);

    // splits of inputs
    launch_split(x,     xh,    xl,    SEQ * DIM);
    launch_split(wq_a,  wqah,  wqal,  QLR * DIM);
    launch_split(wq_b,  wqbh,  wqbl,  NH * QKH * QLR);
    launch_split(wkv_a, wkvah, wkval, (KVLR + DR) * DIM);
    launch_split(wkv_b, wkvbh, wkvbl, NH * (DN + DV) * KVLR);
    launch_split(wo,    woh,   wol,   DIM * NH * DV);

    const dim3 blk(256);

    gemm_bf16x3<<<dim3(QLR / 128, SEQ / 128), blk>>>(
        xh, xl, wqah, wqal, nullptr, qah, qal, SEQ, QLR, DIM, DIM, DIM, QLR);
    gemm_bf16x3<<<dim3((NH * QKH) / 128, SEQ / 128), blk>>>(
        qah, qal, wqbh, wqbl, qb, nullptr, nullptr, SEQ, NH * QKH, QLR, QLR, QLR, NH * QKH);
    gemm_bf16x3<<<dim3((KVLR + DR + 127) / 128, SEQ / 128), blk>>>(
        xh, xl, wkvah, wkval, kvf, kvfh, kvfl, SEQ, KVLR + DR, DIM, DIM, DIM, KVLR + DR);
    rope_kernel<<<SEQ, 256>>>(qb, kvf, kpe, fcos, fsin);
    gemm_bf16x3<<<dim3((NH * (DN + DV)) / 128, SEQ / 128), blk>>>(
        kvfh, kvfl, wkvbh, wkvbl, kvb, nullptr, nullptr,
        SEQ, NH * (DN + DV), KVLR, KVLR + DR, KVLR, NH * (DN + DV));
    lam_kernel<<<1, 32>>>(lqn, lqr, lkn, lkr);

    // tensor-core attention (writes hi/lo split directly)
    const int asmem = ASMEM_ELEMS * (int)sizeof(__nv_bfloat16);
    cudaFuncSetAttribute(attn_mma_kernel, cudaFuncAttributeMaxDynamicSharedMemorySize, asmem);
    attn_mma_kernel<<<dim3(8, NH), 256, asmem>>>(qb, kvb, kpe, attnh, attnl, lamp);

    gemm_bf16x3<<<dim3(DIM / 128, SEQ / 128), blk>>>(
        attnh, attnl, woh, wol, out, nullptr, nullptr, SEQ, DIM, DIM, DIM, DIM, DIM);
}

// round 9
// speedup vs baseline: 2.6539x; 1.1448x over previous
#include <cuda_runtime.h>
#include <cuda_bf16.h>
#include <math.h>

#define SEQ   2048
#define DIM   2048
#define NH    16
#define QLR   768
#define KVLR  512
#define DN    128
#define DR    64
#define DV    128
#define QKH   192
#define HALF  96

#define SCALEF 0.0721687836487032f           // 192^-0.5
#define LAMBDA_INIT_F 0.556058204155754f     // 0.8 - 0.6*exp(-0.9)
#define ONE_MINUS_LI  0.443941795844246f

// ---------------- scratch (no allocations allowed) ----------------
__device__ float g_q[SEQ * NH * QKH];        // q (roped in place)
__device__ float g_kvfull[SEQ * (KVLR + DR)];
__device__ float g_kvb[SEQ * NH * (DN + DV)];
__device__ float g_kpe[SEQ * DR];
__device__ float g_lam;

// bf16 hi/lo operand buffers
__device__ __nv_bfloat16 g_xh[SEQ * DIM],     g_xl[SEQ * DIM];
__device__ __nv_bfloat16 g_qah[SEQ * QLR],    g_qal[SEQ * QLR];
__device__ __nv_bfloat16 g_kvfh[SEQ * (KVLR + DR)], g_kvfl[SEQ * (KVLR + DR)];
__device__ __nv_bfloat16 g_attnh[SEQ * NH * DV],    g_attnl[SEQ * NH * DV];
__device__ __nv_bfloat16 g_wqah[QLR * DIM],   g_wqal[QLR * DIM];
__device__ __nv_bfloat16 g_wqbh[NH * QKH * QLR], g_wqbl[NH * QKH * QLR];
__device__ __nv_bfloat16 g_wkvah[(KVLR + DR) * DIM], g_wkval[(KVLR + DR) * DIM];
__device__ __nv_bfloat16 g_wkvbh[NH * (DN + DV) * KVLR], g_wkvbl[NH * (DN + DV) * KVLR];
__device__ __nv_bfloat16 g_woh[DIM * NH * DV], g_wol[DIM * NH * DV];

// ---------------- helpers ----------------
__device__ __forceinline__ void mma16816(float* d, const unsigned* a, const unsigned* b) {
    asm volatile(
        "mma.sync.aligned.m16n8k16.row.col.f32.bf16.bf16.f32 "
        "{%0,%1,%2,%3},{%4,%5,%6,%7},{%8,%9},{%0,%1,%2,%3};\n"
        : "+f"(d[0]), "+f"(d[1]), "+f"(d[2]), "+f"(d[3])
        : "r"(a[0]), "r"(a[1]), "r"(a[2]), "r"(a[3]), "r"(b[0]), "r"(b[1]));
}

__device__ __forceinline__ void store_split2(__nv_bfloat16* H, __nv_bfloat16* L,
                                             size_t off, float x, float y) {
    __nv_bfloat16 hx = __float2bfloat16(x), hy = __float2bfloat16(y);
    float rx = x - __bfloat162float(hx), ry = y - __bfloat162float(hy);
    __nv_bfloat162 hv, lv;
    hv.x = hx; hv.y = hy;
    lv.x = __float2bfloat16(rx); lv.y = __float2bfloat16(ry);
    *(__nv_bfloat162*)&H[off] = hv;
    *(__nv_bfloat162*)&L[off] = lv;
}

__device__ __forceinline__ unsigned packbf(float a, float b) {
    __nv_bfloat162 t = __floats2bfloat162_rn(a, b);
    return *(unsigned*)&t;
}

__device__ __forceinline__ void packsplit(float a, float b, unsigned& h, unsigned& l) {
    __nv_bfloat16 ha = __float2bfloat16(a), hb = __float2bfloat16(b);
    __nv_bfloat162 hv; hv.x = ha; hv.y = hb;
    h = *(unsigned*)&hv;
    l = packbf(a - __bfloat162float(ha), b - __bfloat162float(hb));
}

__device__ __forceinline__ void cpasync16(unsigned smem_addr, const void* gptr, int srcsize) {
    asm volatile("cp.async.cg.shared.global [%0], [%1], 16, %2;\n"
                 :: "r"(smem_addr), "l"(gptr), "r"(srcsize));
}
__device__ __forceinline__ void cpcommit() {
    asm volatile("cp.async.commit_group;\n");
}
__device__ __forceinline__ void cpwait1() {
    asm volatile("cp.async.wait_group 1;\n");
}

// ---------------- fp32 -> bf16 hi/lo split ----------------
__global__ void split_kernel(const float* __restrict__ X,
                             __nv_bfloat16* __restrict__ H,
                             __nv_bfloat16* __restrict__ L, int n4) {
    int i = blockIdx.x * blockDim.x + threadIdx.x;
    if (i < n4) {
        float4 v = ((const float4*)X)[i];
        store_split2(H, L, (size_t)i * 4, v.x, v.y);
        store_split2(H, L, (size_t)i * 4 + 2, v.z, v.w);
    }
}

// ---------------- tensor-core GEMM with cp.async double buffering ----------------
// C[M,N] = A[M,K] @ B[N,K]^T ; bf16x3 fp32-emulation; 128x128 tile, BK=32, 2 stages.
#define GBUF (128 * 40)

__global__ __launch_bounds__(256) void gemm_bf16x3(
    const __nv_bfloat16* __restrict__ Ah, const __nv_bfloat16* __restrict__ Al,
    const __nv_bfloat16* __restrict__ Bh, const __nv_bfloat16* __restrict__ Bl,
    float* __restrict__ C, __nv_bfloat16* __restrict__ Ch, __nv_bfloat16* __restrict__ Cl,
    int M, int N, int K, int lda, int ldb, int ldc)
{
    extern __shared__ __align__(16) __nv_bfloat16 gs[];  // 8 buffers: [stage][Ah,Al,Bh,Bl]

    const int tid  = threadIdx.x;
    const int m0   = blockIdx.y * 128;
    const int n0   = blockIdx.x * 128;
    const int lane = tid & 31;
    const int warp = tid >> 5;
    const int wm   = (warp >> 2) * 64;
    const int wn   = (warp & 3) * 32;
    const int grp  = lane >> 2;
    const int qp   = lane & 3;

    float acc[4][4][4];
#pragma unroll
    for (int f = 0; f < 4; f++)
#pragma unroll
        for (int g = 0; g < 4; g++)
#pragma unroll
            for (int e = 0; e < 4; e++) acc[f][g][e] = 0.f;

    const unsigned gs_base = (unsigned)__cvta_generic_to_shared(gs);

    auto issue_stage = [&](int s, int kt) {
        const unsigned sbase = gs_base + (unsigned)(s * 4 * GBUF) * 2u;
#pragma unroll
        for (int i = 0; i < 4; i++) {
            const int c = tid + i * 256;           // A chunks
            const int halfb = c >> 9;
            const int w = c & 511;
            const int row = w >> 2, kc = (w & 3) * 8;
            const __nv_bfloat16* src = (halfb ? Al : Ah) + (size_t)(m0 + row) * lda + kt + kc;
            const unsigned dst = sbase + (unsigned)(halfb * GBUF + row * 40 + kc) * 2u;
            cpasync16(dst, src, 16);
        }
#pragma unroll
        for (int i = 0; i < 4; i++) {
            const int c = tid + i * 256;           // B chunks
            const int halfb = c >> 9;
            const int w = c & 511;
            const int row = w >> 2, kc = (w & 3) * 8;
            const __nv_bfloat16* src = (halfb ? Bl : Bh) + (size_t)(n0 + row) * ldb + kt + kc;
            const unsigned dst = sbase + (unsigned)((2 + halfb) * GBUF + row * 40 + kc) * 2u;
            cpasync16(dst, src, (n0 + row < N) ? 16 : 0);
        }
        cpcommit();
    };

    issue_stage(0, 0);

    int s = 0;
    for (int kt = 0; kt < K; kt += 32, s ^= 1) {
        if (kt + 32 < K) issue_stage(s ^ 1, kt + 32);
        else cpcommit();                 // keep group-count accounting uniform
        cpwait1();                       // stage s resident
        __syncthreads();

        const __nv_bfloat16* sAh = gs + (s * 4 + 0) * GBUF;
        const __nv_bfloat16* sAl = gs + (s * 4 + 1) * GBUF;
        const __nv_bfloat16* sBh = gs + (s * 4 + 2) * GBUF;
        const __nv_bfloat16* sBl = gs + (s * 4 + 3) * GBUF;

#pragma unroll
        for (int kk = 0; kk < 32; kk += 16) {
            unsigned ah[4][4], al[4][4], bh[4][2], bl[4][2];
#pragma unroll
            for (int f = 0; f < 4; f++) {
                const int r0 = (wm + f * 16 + grp) * 40 + kk + qp * 2;
                const int r1 = r0 + 8 * 40;
                ah[f][0] = *(const unsigned*)&sAh[r0];
                ah[f][1] = *(const unsigned*)&sAh[r1];
                ah[f][2] = *(const unsigned*)&sAh[r0 + 8];
                ah[f][3] = *(const unsigned*)&sAh[r1 + 8];
                al[f][0] = *(const unsigned*)&sAl[r0];
                al[f][1] = *(const unsigned*)&sAl[r1];
                al[f][2] = *(const unsigned*)&sAl[r0 + 8];
                al[f][3] = *(const unsigned*)&sAl[r1 + 8];
            }
#pragma unroll
            for (int g = 0; g < 4; g++) {
                const int nb = (wn + g * 8 + grp) * 40 + kk + qp * 2;
                bh[g][0] = *(const unsigned*)&sBh[nb];
                bh[g][1] = *(const unsigned*)&sBh[nb + 8];
                bl[g][0] = *(const unsigned*)&sBl[nb];
                bl[g][1] = *(const unsigned*)&sBl[nb + 8];
            }
#pragma unroll
            for (int f = 0; f < 4; f++)
#pragma unroll
                for (int g = 0; g < 4; g++) {
                    mma16816(acc[f][g], ah[f], bh[g]);
                    mma16816(acc[f][g], ah[f], bl[g]);
                    mma16816(acc[f][g], al[f], bh[g]);
                }
        }
        __syncthreads();   // compute on stage s done before next prefetch overwrites it
    }

#pragma unroll
    for (int f = 0; f < 4; f++)
#pragma unroll
        for (int g = 0; g < 4; g++) {
            const int r0  = m0 + wm + f * 16 + grp;
            const int col = n0 + wn + g * 8 + qp * 2;
            if (col < N) {
                const float* a = acc[f][g];
                if (C) {
                    *(float2*)&C[(size_t)r0 * ldc + col]       = make_float2(a[0], a[1]);
                    *(float2*)&C[(size_t)(r0 + 8) * ldc + col] = make_float2(a[2], a[3]);
                }
                if (Ch) {
                    store_split2(Ch, Cl, (size_t)r0 * ldc + col, a[0], a[1]);
                    store_split2(Ch, Cl, (size_t)(r0 + 8) * ldc + col, a[2], a[3]);
                }
            }
        }
}

// ---------------- RoPE (interleaved pairs) ----------------
__global__ void rope_kernel(float* __restrict__ q, const float* __restrict__ kvfull,
                            float* __restrict__ kpe,
                            const float* __restrict__ cosb, const float* __restrict__ sinb)
{
    const int s = blockIdx.x;
    for (int idx = threadIdx.x; idx < NH * 32 + 32; idx += blockDim.x) {
        if (idx < NH * 32) {
            const int h = idx >> 5, p = idx & 31;
            const float c = cosb[s * 32 + p], sn = sinb[s * 32 + p];
            float* base = q + (long)s * (NH * QKH) + h * QKH + DN;
            const float xr = base[2 * p], xi = base[2 * p + 1];
            base[2 * p]     = xr * c - xi * sn;
            base[2 * p + 1] = xr * sn + xi * c;
        } else {
            const int p = idx - NH * 32;
            const float c = cosb[s * 32 + p], sn = sinb[s * 32 + p];
            const float* kb = kvfull + (long)s * (KVLR + DR) + KVLR;
            const float xr = kb[2 * p], xi = kb[2 * p + 1];
            kpe[s * DR + 2 * p]     = xr * c - xi * sn;
            kpe[s * DR + 2 * p + 1] = xr * sn + xi * c;
        }
    }
}

// ---------------- lambda scalar ----------------
__global__ void lam_kernel(const float* __restrict__ lqn, const float* __restrict__ lqr,
                           const float* __restrict__ lkn, const float* __restrict__ lkr)
{
    if (threadIdx.x == 0) {
        float d1 = 0.f, d2 = 0.f;
        for (int i = 0; i < DN; i++) d1 += lqn[i] * lkn[i];
        for (int i = 0; i < DR; i++) d2 += lqr[i] * lkr[i];
        g_lam = expf(d1) - expf(d2) + LAMBDA_INIT_F;
    }
}

// ---------------- tensor-core dual-softmax flash attention (unchanged from R7) ----------------
#define ABQ 128
#define ABK 64
#define KSTR 200
#define VSTR 72
#define ASMEM_ELEMS (2*ABQ*KSTR + 2*ABK*KSTR + 2*DV*VSTR)

__global__ __launch_bounds__(256, 1) void attn_mma_kernel(
    const float* __restrict__ q, const float* __restrict__ kvb,
    const float* __restrict__ kpe,
    __nv_bfloat16* __restrict__ outh, __nv_bfloat16* __restrict__ outl,
    const float* __restrict__ lamp)
{
    extern __shared__ __nv_bfloat16 sb[];
    __nv_bfloat16* Qh  = sb;
    __nv_bfloat16* Ql  = Qh  + ABQ * KSTR;
    __nv_bfloat16* Kh  = Ql  + ABQ * KSTR;
    __nv_bfloat16* Kl  = Kh  + ABK * KSTR;
    __nv_bfloat16* VTh = Kl  + ABK * KSTR;
    __nv_bfloat16* VTl = VTh + DV * VSTR;

    const int tid  = threadIdx.x;
    const int lane = tid & 31;
    const int warp = tid >> 5;
    const int grp  = lane >> 2;
    const int tig  = lane & 3;
    const int wm   = warp * 16;
    const int h    = blockIdx.y;
    const float lam = *lamp;

    for (int half = 0; half < 2; half++) {
        const int qi = (half == 0) ? (int)blockIdx.x : (15 - (int)blockIdx.x);
        const int s0 = qi * ABQ;

        __syncthreads();

        {
            const int r  = tid >> 1;
            const int d0 = (tid & 1) * 96;
            const float* src = q + (size_t)(s0 + r) * (NH * QKH) + h * QKH + d0;
#pragma unroll
            for (int d = 0; d < 96; d += 2)
                store_split2(Qh, Ql, (size_t)r * KSTR + d0 + d, src[d], src[d + 1]);
        }

        float o1[16][4], o2[16][4];
#pragma unroll
        for (int v = 0; v < 16; v++)
#pragma unroll
            for (int e = 0; e < 4; e++) { o1[v][e] = 0.f; o2[v][e] = 0.f; }
        float m_[2][2] = {{-1e30f, -1e30f}, {-1e30f, -1e30f}};
        float l_[2][2] = {{0.f, 0.f}, {0.f, 0.f}};

        const int ntiles = s0 / ABK + 2;
        for (int tix = 0; tix < ntiles; tix++) {
            const int t0 = tix * ABK;
            if (tix > 0) __syncthreads();
            {
                const int k  = tid >> 2;
                const int d0 = (tid & 3) * 48;
                const float* kn = kvb + (size_t)(t0 + k) * (NH * 256) + h * 256;
                const float* kp = kpe + (size_t)(t0 + k) * DR;
#pragma unroll
                for (int i = 0; i < 48; i += 2) {
                    const int d = d0 + i;
                    const float a = (d < 128)     ? kn[d]     : kp[d - 128];
                    const float b = (d + 1 < 128) ? kn[d + 1] : kp[d - 127];
                    store_split2(Kh, Kl, (size_t)k * KSTR + d, a, b);
                }
                const int vd0 = (tid & 3) * 32;
#pragma unroll
                for (int i = 0; i < 32; i++) {
                    const float val = kn[128 + vd0 + i];
                    const __nv_bfloat16 hv = __float2bfloat16(val);
                    VTh[(vd0 + i) * VSTR + k] = hv;
                    VTl[(vd0 + i) * VSTR + k] =
                        __float2bfloat16(val - __bfloat162float(hv));
                }
            }
            __syncthreads();

            if (t0 <= s0 + wm + 15) {
#pragma unroll
                for (int br = 0; br < 2; br++) {
                    const int kb = br * HALF;
                    float acc[8][4];
#pragma unroll
                    for (int j = 0; j < 8; j++)
#pragma unroll
                        for (int e = 0; e < 4; e++) acc[j][e] = 0.f;

#pragma unroll
                    for (int t = 0; t < 6; t++) {
                        const int kk = kb + t * 16;
                        unsigned ah[4], al[4];
                        const int qo = (wm + grp) * KSTR + kk + 2 * tig;
                        ah[0] = *(const unsigned*)&Qh[qo];
                        ah[1] = *(const unsigned*)&Qh[qo + 8 * KSTR];
                        ah[2] = *(const unsigned*)&Qh[qo + 8];
                        ah[3] = *(const unsigned*)&Qh[qo + 8 * KSTR + 8];
                        al[0] = *(const unsigned*)&Ql[qo];
                        al[1] = *(const unsigned*)&Ql[qo + 8 * KSTR];
                        al[2] = *(const unsigned*)&Ql[qo + 8];
                        al[3] = *(const unsigned*)&Ql[qo + 8 * KSTR + 8];
#pragma unroll
                        for (int j = 0; j < 8; j++) {
                            unsigned bh[2], bl[2];
                            const int ko = (8 * j + grp) * KSTR + kk + 2 * tig;
                            bh[0] = *(const unsigned*)&Kh[ko];
                            bh[1] = *(const unsigned*)&Kh[ko + 8];
                            bl[0] = *(const unsigned*)&Kl[ko];
                            bl[1] = *(const unsigned*)&Kl[ko + 8];
                            mma16816(acc[j], ah, bh);
                            mma16816(acc[j], ah, bl);
                            mma16816(acc[j], al, bh);
                        }
                    }

                    const int r0 = s0 + wm + grp, r1 = r0 + 8;
#pragma unroll
                    for (int j = 0; j < 8; j++)
#pragma unroll
                        for (int e = 0; e < 4; e++) {
                            const int key = t0 + 8 * j + 2 * tig + (e & 1);
                            const int row = (e < 2) ? r0 : r1;
                            float v = fminf(fmaxf(acc[j][e] * SCALEF, -100.f), 100.f);
                            acc[j][e] = (key > row) ? -1e9f : v;
                        }

                    float mx0 = -1e30f, mx1 = -1e30f;
#pragma unroll
                    for (int j = 0; j < 8; j++) {
                        mx0 = fmaxf(mx0, fmaxf(acc[j][0], acc[j][1]));
                        mx1 = fmaxf(mx1, fmaxf(acc[j][2], acc[j][3]));
                    }
                    mx0 = fmaxf(mx0, __shfl_xor_sync(0xffffffffu, mx0, 1));
                    mx0 = fmaxf(mx0, __shfl_xor_sync(0xffffffffu, mx0, 2));
                    mx1 = fmaxf(mx1, __shfl_xor_sync(0xffffffffu, mx1, 1));
                    mx1 = fmaxf(mx1, __shfl_xor_sync(0xffffffffu, mx1, 2));

                    const float mo0 = m_[br][0], mo1 = m_[br][1];
                    const float mn0 = fmaxf(mo0, mx0), mn1 = fmaxf(mo1, mx1);
                    const float sc0 = __expf(mo0 - mn0), sc1 = __expf(mo1 - mn1);
                    m_[br][0] = mn0; m_[br][1] = mn1;

                    float su0 = 0.f, su1 = 0.f;
#pragma unroll
                    for (int j = 0; j < 8; j++) {
                        float p0 = __expf(acc[j][0] - mn0);
                        float p1 = __expf(acc[j][1] - mn0);
                        float p2 = __expf(acc[j][2] - mn1);
                        float p3 = __expf(acc[j][3] - mn1);
                        acc[j][0] = p0; acc[j][1] = p1; acc[j][2] = p2; acc[j][3] = p3;
                        su0 += p0 + p1; su1 += p2 + p3;
                    }
                    su0 += __shfl_xor_sync(0xffffffffu, su0, 1);
                    su0 += __shfl_xor_sync(0xffffffffu, su0, 2);
                    su1 += __shfl_xor_sync(0xffffffffu, su1, 1);
                    su1 += __shfl_xor_sync(0xffffffffu, su1, 2);
                    l_[br][0] = l_[br][0] * sc0 + su0;
                    l_[br][1] = l_[br][1] * sc1 + su1;

                    float (*ob)[4] = br ? o2 : o1;
#pragma unroll
                    for (int v = 0; v < 16; v++) {
                        ob[v][0] *= sc0; ob[v][1] *= sc0;
                        ob[v][2] *= sc1; ob[v][3] *= sc1;
                    }

                    unsigned pa[4][4], pal[4][4];
#pragma unroll
                    for (int t = 0; t < 4; t++) {
                        packsplit(acc[2 * t][0],     acc[2 * t][1],     pa[t][0], pal[t][0]);
                        packsplit(acc[2 * t][2],     acc[2 * t][3],     pa[t][1], pal[t][1]);
                        packsplit(acc[2 * t + 1][0], acc[2 * t + 1][1], pa[t][2], pal[t][2]);
                        packsplit(acc[2 * t + 1][2], acc[2 * t + 1][3], pa[t][3], pal[t][3]);
                    }

#pragma unroll
                    for (int v = 0; v < 16; v++) {
#pragma unroll
                        for (int t = 0; t < 4; t++) {
                            unsigned bvh[2], bvl[2];
                            const int vo = (8 * v + grp) * VSTR + 16 * t + 2 * tig;
                            bvh[0] = *(const unsigned*)&VTh[vo];
                            bvh[1] = *(const unsigned*)&VTh[vo + 8];
                            bvl[0] = *(const unsigned*)&VTl[vo];
                            bvl[1] = *(const unsigned*)&VTl[vo + 8];
                            mma16816(ob[v], pa[t],  bvh);
                            mma16816(ob[v], pal[t], bvh);
                            mma16816(ob[v], pa[t],  bvl);
                        }
                    }
                }
            }
        }

        const float i10 = 1.f / l_[0][0], i11 = 1.f / l_[0][1];
        const float i20 = lam / l_[1][0], i21 = lam / l_[1][1];
        const int r0 = s0 + wm + grp, r1 = r0 + 8;
#pragma unroll
        for (int v = 0; v < 16; v++) {
            const int col = h * DV + 8 * v + 2 * tig;
            const float a0 = (o1[v][0] * i10 - o2[v][0] * i20) * ONE_MINUS_LI;
            const float a1 = (o1[v][1] * i10 - o2[v][1] * i20) * ONE_MINUS_LI;
            const float a2 = (o1[v][2] * i11 - o2[v][2] * i21) * ONE_MINUS_LI;
            const float a3 = (o1[v][3] * i11 - o2[v][3] * i21) * ONE_MINUS_LI;
            store_split2(outh, outl, (size_t)r0 * (NH * DV) + col, a0, a1);
            store_split2(outh, outl, (size_t)r1 * (NH * DV) + col, a2, a3);
        }
    }
}

// ---------------- launch ----------------
static inline void launch_split(const float* X, __nv_bfloat16* H, __nv_bfloat16* L, int n) {
    const int n4 = n / 4;
    split_kernel<<<(n4 + 255) / 256, 256>>>(X, H, L, n4);
}

extern "C" void kernel_launch(void* const* d_in, const int* in_sizes, int n_in,
                              void* d_out, int out_size)
{
    const float* x     = (const float*)d_in[0];
    const float* wq_a  = (const float*)d_in[1];
    const float* wq_b  = (const float*)d_in[2];
    const float* wkv_a = (const float*)d_in[3];
    const float* wkv_b = (const float*)d_in[4];
    const float* wo    = (const float*)d_in[5];
    const float* lqn   = (const float*)d_in[6];
    const float* lqr   = (const float*)d_in[7];
    const float* lkn   = (const float*)d_in[8];
    const float* lkr   = (const float*)d_in[9];
    const float* fcos  = (const float*)d_in[10];
    const float* fsin  = (const float*)d_in[11];
    float* out = (float*)d_out;

    float *qb, *kvf, *kvb, *kpe, *lamp;
    cudaGetSymbolAddress((void**)&qb,   g_q);
    cudaGetSymbolAddress((void**)&kvf,  g_kvfull);
    cudaGetSymbolAddress((void**)&kvb,  g_kvb);
    cudaGetSymbolAddress((void**)&kpe,  g_kpe);
    cudaGetSymbolAddress((void**)&lamp, g_lam);

    __nv_bfloat16 *xh,*xl,*qah,*qal,*kvfh,*kvfl,*attnh,*attnl;
    __nv_bfloat16 *wqah,*wqal,*wqbh,*wqbl,*wkvah,*wkval,*wkvbh,*wkvbl,*woh,*wol;
    cudaGetSymbolAddress((void**)&xh, g_xh);     cudaGetSymbolAddress((void**)&xl, g_xl);
    cudaGetSymbolAddress((void**)&qah, g_qah);   cudaGetSymbolAddress((void**)&qal, g_qal);
    cudaGetSymbolAddress((void**)&kvfh, g_kvfh); cudaGetSymbolAddress((void**)&kvfl, g_kvfl);
    cudaGetSymbolAddress((void**)&attnh, g_attnh); cudaGetSymbolAddress((void**)&attnl, g_attnl);
    cudaGetSymbolAddress((void**)&wqah, g_wqah); cudaGetSymbolAddress((void**)&wqal, g_wqal);
    cudaGetSymbolAddress((void**)&wqbh, g_wqbh); cudaGetSymbolAddress((void**)&wqbl, g_wqbl);
    cudaGetSymbolAddress((void**)&wkvah, g_wkvah); cudaGetSymbolAddress((void**)&wkval, g_wkval);
    cudaGetSymbolAddress((void**)&wkvbh, g_wkvbh); cudaGetSymbolAddress((void**)&wkvbl, g_wkvbl);
    cudaGetSymbolAddress((void**)&woh, g_woh);   cudaGetSymbolAddress((void**)&wol, g_wol);

    // splits of inputs
    launch_split(x,     xh,    xl,    SEQ * DIM);
    launch_split(wq_a,  wqah,  wqal,  QLR * DIM);
    launch_split(wq_b,  wqbh,  wqbl,  NH * QKH * QLR);
    launch_split(wkv_a, wkvah, wkval, (KVLR + DR) * DIM);
    launch_split(wkv_b, wkvbh, wkvbl, NH * (DN + DV) * KVLR);
    launch_split(wo,    woh,   wol,   DIM * NH * DV);

    const dim3 blk(256);
    const int gsmem = 8 * GBUF * (int)sizeof(__nv_bfloat16);   // 81920 B
    cudaFuncSetAttribute(gemm_bf16x3, cudaFuncAttributeMaxDynamicSharedMemorySize, gsmem);

    gemm_bf16x3<<<dim3(QLR / 128, SEQ / 128), blk, gsmem>>>(
        xh, xl, wqah, wqal, nullptr, qah, qal, SEQ, QLR, DIM, DIM, DIM, QLR);
    gemm_bf16x3<<<dim3((NH * QKH) / 128, SEQ / 128), blk, gsmem>>>(
        qah, qal, wqbh, wqbl, qb, nullptr, nullptr, SEQ, NH * QKH, QLR, QLR, QLR, NH * QKH);
    gemm_bf16x3<<<dim3((KVLR + DR + 127) / 128, SEQ / 128), blk, gsmem>>>(
        xh, xl, wkvah, wkval, kvf, kvfh, kvfl, SEQ, KVLR + DR, DIM, DIM, DIM, KVLR + DR);
    rope_kernel<<<SEQ, 256>>>(qb, kvf, kpe, fcos, fsin);
    gemm_bf16x3<<<dim3((NH * (DN + DV)) / 128, SEQ / 128), blk, gsmem>>>(
        kvfh, kvfl, wkvbh, wkvbl, kvb, nullptr, nullptr,
        SEQ, NH * (DN + DV), KVLR, KVLR + DR, KVLR, NH * (DN + DV));
    lam_kernel<<<1, 32>>>(lqn, lqr, lkn, lkr);

    const int asmem = ASMEM_ELEMS * (int)sizeof(__nv_bfloat16);
    cudaFuncSetAttribute(attn_mma_kernel, cudaFuncAttributeMaxDynamicSharedMemorySize, asmem);
    attn_mma_kernel<<<dim3(8, NH), 256, asmem>>>(qb, kvb, kpe, attnh, attnl, lamp);

    gemm_bf16x3<<<dim3(DIM / 128, SEQ / 128), blk, gsmem>>>(
        attnh, attnl, woh, wol, out, nullptr, nullptr, SEQ, DIM, DIM, DIM, DIM, DIM);
}

// round 10
// speedup vs baseline: 2.7825x; 1.0484x over previous
#include <cuda_runtime.h>
#include <cuda_bf16.h>
#include <math.h>

#define SEQ   2048
#define DIM   2048
#define NH    16
#define QLR   768
#define KVLR  512
#define DN    128
#define DR    64
#define DV    128
#define QKH   192
#define HALF  96

#define SCALEF 0.0721687836487032f           // 192^-0.5
#define LAMBDA_INIT_F 0.556058204155754f     // 0.8 - 0.6*exp(-0.9)
#define ONE_MINUS_LI  0.443941795844246f

// ---------------- scratch (no allocations allowed) ----------------
__device__ float g_q[SEQ * NH * QKH];        // q (roped in place)
__device__ float g_kvfull[SEQ * (KVLR + DR)];
__device__ float g_kvb[SEQ * NH * (DN + DV)];
__device__ float g_kpe[SEQ * DR];
__device__ float g_lam;

// bf16 hi/lo operand buffers
__device__ __nv_bfloat16 g_xh[SEQ * DIM],     g_xl[SEQ * DIM];
__device__ __nv_bfloat16 g_qah[SEQ * QLR],    g_qal[SEQ * QLR];
__device__ __nv_bfloat16 g_kvfh[SEQ * (KVLR + DR)], g_kvfl[SEQ * (KVLR + DR)];
__device__ __nv_bfloat16 g_attnh[SEQ * NH * DV],    g_attnl[SEQ * NH * DV];
__device__ __nv_bfloat16 g_wqah[QLR * DIM],   g_wqal[QLR * DIM];
__device__ __nv_bfloat16 g_wqbh[NH * QKH * QLR], g_wqbl[NH * QKH * QLR];
__device__ __nv_bfloat16 g_wkvah[(KVLR + DR) * DIM], g_wkval[(KVLR + DR) * DIM];
__device__ __nv_bfloat16 g_wkvbh[NH * (DN + DV) * KVLR], g_wkvbl[NH * (DN + DV) * KVLR];
__device__ __nv_bfloat16 g_woh[DIM * NH * DV], g_wol[DIM * NH * DV];

// ---------------- helpers ----------------
__device__ __forceinline__ void mma16816(float* d, const unsigned* a, const unsigned* b) {
    asm volatile(
        "mma.sync.aligned.m16n8k16.row.col.f32.bf16.bf16.f32 "
        "{%0,%1,%2,%3},{%4,%5,%6,%7},{%8,%9},{%0,%1,%2,%3};\n"
        : "+f"(d[0]), "+f"(d[1]), "+f"(d[2]), "+f"(d[3])
        : "r"(a[0]), "r"(a[1]), "r"(a[2]), "r"(a[3]), "r"(b[0]), "r"(b[1]));
}

__device__ __forceinline__ void ldsm4(unsigned* r, unsigned addr) {
    asm volatile("ldmatrix.sync.aligned.m8n8.x4.shared.b16 {%0,%1,%2,%3}, [%4];"
                 : "=r"(r[0]), "=r"(r[1]), "=r"(r[2]), "=r"(r[3]) : "r"(addr));
}
__device__ __forceinline__ void ldsm2(unsigned* r, unsigned addr) {
    asm volatile("ldmatrix.sync.aligned.m8n8.x2.shared.b16 {%0,%1}, [%2];"
                 : "=r"(r[0]), "=r"(r[1]) : "r"(addr));
}

__device__ __forceinline__ void store_split2(__nv_bfloat16* H, __nv_bfloat16* L,
                                             size_t off, float x, float y) {
    __nv_bfloat16 hx = __float2bfloat16(x), hy = __float2bfloat16(y);
    float rx = x - __bfloat162float(hx), ry = y - __bfloat162float(hy);
    __nv_bfloat162 hv, lv;
    hv.x = hx; hv.y = hy;
    lv.x = __float2bfloat16(rx); lv.y = __float2bfloat16(ry);
    *(__nv_bfloat162*)&H[off] = hv;
    *(__nv_bfloat162*)&L[off] = lv;
}

__device__ __forceinline__ unsigned packbf(float a, float b) {
    __nv_bfloat162 t = __floats2bfloat162_rn(a, b);
    return *(unsigned*)&t;
}

__device__ __forceinline__ void packsplit(float a, float b, unsigned& h, unsigned& l) {
    __nv_bfloat16 ha = __float2bfloat16(a), hb = __float2bfloat16(b);
    __nv_bfloat162 hv; hv.x = ha; hv.y = hb;
    h = *(unsigned*)&hv;
    l = packbf(a - __bfloat162float(ha), b - __bfloat162float(hb));
}

__device__ __forceinline__ void cpasync16(unsigned smem_addr, const void* gptr, int srcsize) {
    asm volatile("cp.async.cg.shared.global [%0], [%1], 16, %2;\n"
                 :: "r"(smem_addr), "l"(gptr), "r"(srcsize));
}
__device__ __forceinline__ void cpcommit() {
    asm volatile("cp.async.commit_group;\n");
}
__device__ __forceinline__ void cpwait1() {
    asm volatile("cp.async.wait_group 1;\n");
}

// ---------------- fp32 -> bf16 hi/lo split ----------------
__global__ void split_kernel(const float* __restrict__ X,
                             __nv_bfloat16* __restrict__ H,
                             __nv_bfloat16* __restrict__ L, int n4) {
    int i = blockIdx.x * blockDim.x + threadIdx.x;
    if (i < n4) {
        float4 v = ((const float4*)X)[i];
        store_split2(H, L, (size_t)i * 4, v.x, v.y);
        store_split2(H, L, (size_t)i * 4 + 2, v.z, v.w);
    }
}

// ---------------- tensor-core GEMM with cp.async double buffering + ldmatrix ----------------
// C[M,N] = A[M,K] @ B[N,K]^T ; bf16x3 fp32-emulation; 128x128 tile, BK=32, 2 stages.
#define GBUF (128 * 40)

__global__ __launch_bounds__(256) void gemm_bf16x3(
    const __nv_bfloat16* __restrict__ Ah, const __nv_bfloat16* __restrict__ Al,
    const __nv_bfloat16* __restrict__ Bh, const __nv_bfloat16* __restrict__ Bl,
    float* __restrict__ C, __nv_bfloat16* __restrict__ Ch, __nv_bfloat16* __restrict__ Cl,
    int M, int N, int K, int lda, int ldb, int ldc)
{
    extern __shared__ __align__(16) __nv_bfloat16 gs[];  // 8 buffers: [stage][Ah,Al,Bh,Bl]

    const int tid  = threadIdx.x;
    const int m0   = blockIdx.y * 128;
    const int n0   = blockIdx.x * 128;
    const int lane = tid & 31;
    const int warp = tid >> 5;
    const int wm   = (warp >> 2) * 64;
    const int wn   = (warp & 3) * 32;
    const int grp  = lane >> 2;
    const int qp   = lane & 3;

    float acc[4][4][4];
#pragma unroll
    for (int f = 0; f < 4; f++)
#pragma unroll
        for (int g = 0; g < 4; g++)
#pragma unroll
            for (int e = 0; e < 4; e++) acc[f][g][e] = 0.f;

    const unsigned gs_base = (unsigned)__cvta_generic_to_shared(gs);

    auto issue_stage = [&](int s, int kt) {
        const unsigned sbase = gs_base + (unsigned)(s * 4 * GBUF) * 2u;
#pragma unroll
        for (int i = 0; i < 4; i++) {
            const int c = tid + i * 256;           // A chunks
            const int halfb = c >> 9;
            const int w = c & 511;
            const int row = w >> 2, kc = (w & 3) * 8;
            const __nv_bfloat16* src = (halfb ? Al : Ah) + (size_t)(m0 + row) * lda + kt + kc;
            const unsigned dst = sbase + (unsigned)(halfb * GBUF + row * 40 + kc) * 2u;
            cpasync16(dst, src, 16);
        }
#pragma unroll
        for (int i = 0; i < 4; i++) {
            const int c = tid + i * 256;           // B chunks
            const int halfb = c >> 9;
            const int w = c & 511;
            const int row = w >> 2, kc = (w & 3) * 8;
            const __nv_bfloat16* src = (halfb ? Bl : Bh) + (size_t)(n0 + row) * ldb + kt + kc;
            const unsigned dst = sbase + (unsigned)((2 + halfb) * GBUF + row * 40 + kc) * 2u;
            cpasync16(dst, src, (n0 + row < N) ? 16 : 0);
        }
        cpcommit();
    };

    issue_stage(0, 0);

    // ldmatrix per-lane source coordinates (constant across iterations)
    const int arow = lane & 15;                 // A: 16 rows, two k-halves
    const int acol = (lane >> 4) * 8;
    const int brow = lane & 7;                  // B: 8 rows, two k-halves (lanes 0-15)
    const int bcol = ((lane >> 3) & 1) * 8;

    int s = 0;
    for (int kt = 0; kt < K; kt += 32, s ^= 1) {
        if (kt + 32 < K) issue_stage(s ^ 1, kt + 32);
        else cpcommit();                 // keep group-count accounting uniform
        cpwait1();                       // stage s resident
        __syncthreads();

        const unsigned sAh_a = gs_base + (unsigned)((s * 4 + 0) * GBUF) * 2u;
        const unsigned sAl_a = gs_base + (unsigned)((s * 4 + 1) * GBUF) * 2u;
        const unsigned sBh_a = gs_base + (unsigned)((s * 4 + 2) * GBUF) * 2u;
        const unsigned sBl_a = gs_base + (unsigned)((s * 4 + 3) * GBUF) * 2u;

#pragma unroll
        for (int kk = 0; kk < 32; kk += 16) {
            unsigned ah[4][4], al[4][4], bh[4][2], bl[4][2];
#pragma unroll
            for (int f = 0; f < 4; f++) {
                const unsigned o = (unsigned)(((wm + f * 16 + arow) * 40 + kk + acol) * 2);
                ldsm4(ah[f], sAh_a + o);
                ldsm4(al[f], sAl_a + o);
            }
#pragma unroll
            for (int g = 0; g < 4; g++) {
                const unsigned o = (unsigned)(((wn + g * 8 + brow) * 40 + kk + bcol) * 2);
                ldsm2(bh[g], sBh_a + o);
                ldsm2(bl[g], sBl_a + o);
            }
#pragma unroll
            for (int f = 0; f < 4; f++)
#pragma unroll
                for (int g = 0; g < 4; g++) {
                    mma16816(acc[f][g], ah[f], bh[g]);
                    mma16816(acc[f][g], ah[f], bl[g]);
                    mma16816(acc[f][g], al[f], bh[g]);
                }
        }
        __syncthreads();   // compute on stage s done before next prefetch overwrites it
    }

#pragma unroll
    for (int f = 0; f < 4; f++)
#pragma unroll
        for (int g = 0; g < 4; g++) {
            const int r0  = m0 + wm + f * 16 + grp;
            const int col = n0 + wn + g * 8 + qp * 2;
            if (col < N) {
                const float* a = acc[f][g];
                if (C) {
                    *(float2*)&C[(size_t)r0 * ldc + col]       = make_float2(a[0], a[1]);
                    *(float2*)&C[(size_t)(r0 + 8) * ldc + col] = make_float2(a[2], a[3]);
                }
                if (Ch) {
                    store_split2(Ch, Cl, (size_t)r0 * ldc + col, a[0], a[1]);
                    store_split2(Ch, Cl, (size_t)(r0 + 8) * ldc + col, a[2], a[3]);
                }
            }
        }
}

// ---------------- RoPE (interleaved pairs) ----------------
__global__ void rope_kernel(float* __restrict__ q, const float* __restrict__ kvfull,
                            float* __restrict__ kpe,
                            const float* __restrict__ cosb, const float* __restrict__ sinb)
{
    const int s = blockIdx.x;
    for (int idx = threadIdx.x; idx < NH * 32 + 32; idx += blockDim.x) {
        if (idx < NH * 32) {
            const int h = idx >> 5, p = idx & 31;
            const float c = cosb[s * 32 + p], sn = sinb[s * 32 + p];
            float* base = q + (long)s * (NH * QKH) + h * QKH + DN;
            const float xr = base[2 * p], xi = base[2 * p + 1];
            base[2 * p]     = xr * c - xi * sn;
            base[2 * p + 1] = xr * sn + xi * c;
        } else {
            const int p = idx - NH * 32;
            const float c = cosb[s * 32 + p], sn = sinb[s * 32 + p];
            const float* kb = kvfull + (long)s * (KVLR + DR) + KVLR;
            const float xr = kb[2 * p], xi = kb[2 * p + 1];
            kpe[s * DR + 2 * p]     = xr * c - xi * sn;
            kpe[s * DR + 2 * p + 1] = xr * sn + xi * c;
        }
    }
}

// ---------------- lambda scalar ----------------
__global__ void lam_kernel(const float* __restrict__ lqn, const float* __restrict__ lqr,
                           const float* __restrict__ lkn, const float* __restrict__ lkr)
{
    if (threadIdx.x == 0) {
        float d1 = 0.f, d2 = 0.f;
        for (int i = 0; i < DN; i++) d1 += lqn[i] * lkn[i];
        for (int i = 0; i < DR; i++) d2 += lqr[i] * lkr[i];
        g_lam = expf(d1) - expf(d2) + LAMBDA_INIT_F;
    }
}

// ---------------- tensor-core dual-softmax flash attention (unchanged from R7) ----------------
#define ABQ 128
#define ABK 64
#define KSTR 200
#define VSTR 72
#define ASMEM_ELEMS (2*ABQ*KSTR + 2*ABK*KSTR + 2*DV*VSTR)

__global__ __launch_bounds__(256, 1) void attn_mma_kernel(
    const float* __restrict__ q, const float* __restrict__ kvb,
    const float* __restrict__ kpe,
    __nv_bfloat16* __restrict__ outh, __nv_bfloat16* __restrict__ outl,
    const float* __restrict__ lamp)
{
    extern __shared__ __nv_bfloat16 sb[];
    __nv_bfloat16* Qh  = sb;
    __nv_bfloat16* Ql  = Qh  + ABQ * KSTR;
    __nv_bfloat16* Kh  = Ql  + ABQ * KSTR;
    __nv_bfloat16* Kl  = Kh  + ABK * KSTR;
    __nv_bfloat16* VTh = Kl  + ABK * KSTR;
    __nv_bfloat16* VTl = VTh + DV * VSTR;

    const int tid  = threadIdx.x;
    const int lane = tid & 31;
    const int warp = tid >> 5;
    const int grp  = lane >> 2;
    const int tig  = lane & 3;
    const int wm   = warp * 16;
    const int h    = blockIdx.y;
    const float lam = *lamp;

    for (int half = 0; half < 2; half++) {
        const int qi = (half == 0) ? (int)blockIdx.x : (15 - (int)blockIdx.x);
        const int s0 = qi * ABQ;

        __syncthreads();

        {
            const int r  = tid >> 1;
            const int d0 = (tid & 1) * 96;
            const float* src = q + (size_t)(s0 + r) * (NH * QKH) + h * QKH + d0;
#pragma unroll
            for (int d = 0; d < 96; d += 2)
                store_split2(Qh, Ql, (size_t)r * KSTR + d0 + d, src[d], src[d + 1]);
        }

        float o1[16][4], o2[16][4];
#pragma unroll
        for (int v = 0; v < 16; v++)
#pragma unroll
            for (int e = 0; e < 4; e++) { o1[v][e] = 0.f; o2[v][e] = 0.f; }
        float m_[2][2] = {{-1e30f, -1e30f}, {-1e30f, -1e30f}};
        float l_[2][2] = {{0.f, 0.f}, {0.f, 0.f}};

        const int ntiles = s0 / ABK + 2;
        for (int tix = 0; tix < ntiles; tix++) {
            const int t0 = tix * ABK;
            if (tix > 0) __syncthreads();
            {
                const int k  = tid >> 2;
                const int d0 = (tid & 3) * 48;
                const float* kn = kvb + (size_t)(t0 + k) * (NH * 256) + h * 256;
                const float* kp = kpe + (size_t)(t0 + k) * DR;
#pragma unroll
                for (int i = 0; i < 48; i += 2) {
                    const int d = d0 + i;
                    const float a = (d < 128)     ? kn[d]     : kp[d - 128];
                    const float b = (d + 1 < 128) ? kn[d + 1] : kp[d - 127];
                    store_split2(Kh, Kl, (size_t)k * KSTR + d, a, b);
                }
                const int vd0 = (tid & 3) * 32;
#pragma unroll
                for (int i = 0; i < 32; i++) {
                    const float val = kn[128 + vd0 + i];
                    const __nv_bfloat16 hv = __float2bfloat16(val);
                    VTh[(vd0 + i) * VSTR + k] = hv;
                    VTl[(vd0 + i) * VSTR + k] =
                        __float2bfloat16(val - __bfloat162float(hv));
                }
            }
            __syncthreads();

            if (t0 <= s0 + wm + 15) {
#pragma unroll
                for (int br = 0; br < 2; br++) {
                    const int kb = br * HALF;
                    float acc[8][4];
#pragma unroll
                    for (int j = 0; j < 8; j++)
#pragma unroll
                        for (int e = 0; e < 4; e++) acc[j][e] = 0.f;

#pragma unroll
                    for (int t = 0; t < 6; t++) {
                        const int kk = kb + t * 16;
                        unsigned ah[4], al[4];
                        const int qo = (wm + grp) * KSTR + kk + 2 * tig;
                        ah[0] = *(const unsigned*)&Qh[qo];
                        ah[1] = *(const unsigned*)&Qh[qo + 8 * KSTR];
                        ah[2] = *(const unsigned*)&Qh[qo + 8];
                        ah[3] = *(const unsigned*)&Qh[qo + 8 * KSTR + 8];
                        al[0] = *(const unsigned*)&Ql[qo];
                        al[1] = *(const unsigned*)&Ql[qo + 8 * KSTR];
                        al[2] = *(const unsigned*)&Ql[qo + 8];
                        al[3] = *(const unsigned*)&Ql[qo + 8 * KSTR + 8];
#pragma unroll
                        for (int j = 0; j < 8; j++) {
                            unsigned bh[2], bl[2];
                            const int ko = (8 * j + grp) * KSTR + kk + 2 * tig;
                            bh[0] = *(const unsigned*)&Kh[ko];
                            bh[1] = *(const unsigned*)&Kh[ko + 8];
                            bl[0] = *(const unsigned*)&Kl[ko];
                            bl[1] = *(const unsigned*)&Kl[ko + 8];
                            mma16816(acc[j], ah, bh);
                            mma16816(acc[j], ah, bl);
                            mma16816(acc[j], al, bh);
                        }
                    }

                    const int r0 = s0 + wm + grp, r1 = r0 + 8;
#pragma unroll
                    for (int j = 0; j < 8; j++)
#pragma unroll
                        for (int e = 0; e < 4; e++) {
                            const int key = t0 + 8 * j + 2 * tig + (e & 1);
                            const int row = (e < 2) ? r0 : r1;
                            float v = fminf(fmaxf(acc[j][e] * SCALEF, -100.f), 100.f);
                            acc[j][e] = (key > row) ? -1e9f : v;
                        }

                    float mx0 = -1e30f, mx1 = -1e30f;
#pragma unroll
                    for (int j = 0; j < 8; j++) {
                        mx0 = fmaxf(mx0, fmaxf(acc[j][0], acc[j][1]));
                        mx1 = fmaxf(mx1, fmaxf(acc[j][2], acc[j][3]));
                    }
                    mx0 = fmaxf(mx0, __shfl_xor_sync(0xffffffffu, mx0, 1));
                    mx0 = fmaxf(mx0, __shfl_xor_sync(0xffffffffu, mx0, 2));
                    mx1 = fmaxf(mx1, __shfl_xor_sync(0xffffffffu, mx1, 1));
                    mx1 = fmaxf(mx1, __shfl_xor_sync(0xffffffffu, mx1, 2));

                    const float mo0 = m_[br][0], mo1 = m_[br][1];
                    const float mn0 = fmaxf(mo0, mx0), mn1 = fmaxf(mo1, mx1);
                    const float sc0 = __expf(mo0 - mn0), sc1 = __expf(mo1 - mn1);
                    m_[br][0] = mn0; m_[br][1] = mn1;

                    float su0 = 0.f, su1 = 0.f;
#pragma unroll
                    for (int j = 0; j < 8; j++) {
                        float p0 = __expf(acc[j][0] - mn0);
                        float p1 = __expf(acc[j][1] - mn0);
                        float p2 = __expf(acc[j][2] - mn1);
                        float p3 = __expf(acc[j][3] - mn1);
                        acc[j][0] = p0; acc[j][1] = p1; acc[j][2] = p2; acc[j][3] = p3;
                        su0 += p0 + p1; su1 += p2 + p3;
                    }
                    su0 += __shfl_xor_sync(0xffffffffu, su0, 1);
                    su0 += __shfl_xor_sync(0xffffffffu, su0, 2);
                    su1 += __shfl_xor_sync(0xffffffffu, su1, 1);
                    su1 += __shfl_xor_sync(0xffffffffu, su1, 2);
                    l_[br][0] = l_[br][0] * sc0 + su0;
                    l_[br][1] = l_[br][1] * sc1 + su1;

                    float (*ob)[4] = br ? o2 : o1;
#pragma unroll
                    for (int v = 0; v < 16; v++) {
                        ob[v][0] *= sc0; ob[v][1] *= sc0;
                        ob[v][2] *= sc1; ob[v][3] *= sc1;
                    }

                    unsigned pa[4][4], pal[4][4];
#pragma unroll
                    for (int t = 0; t < 4; t++) {
                        packsplit(acc[2 * t][0],     acc[2 * t][1],     pa[t][0], pal[t][0]);
                        packsplit(acc[2 * t][2],     acc[2 * t][3],     pa[t][1], pal[t][1]);
                        packsplit(acc[2 * t + 1][0], acc[2 * t + 1][1], pa[t][2], pal[t][2]);
                        packsplit(acc[2 * t + 1][2], acc[2 * t + 1][3], pa[t][3], pal[t][3]);
                    }

#pragma unroll
                    for (int v = 0; v < 16; v++) {
#pragma unroll
                        for (int t = 0; t < 4; t++) {
                            unsigned bvh[2], bvl[2];
                            const int vo = (8 * v + grp) * VSTR + 16 * t + 2 * tig;
                            bvh[0] = *(const unsigned*)&VTh[vo];
                            bvh[1] = *(const unsigned*)&VTh[vo + 8];
                            bvl[0] = *(const unsigned*)&VTl[vo];
                            bvl[1] = *(const unsigned*)&VTl[vo + 8];
                            mma16816(ob[v], pa[t],  bvh);
                            mma16816(ob[v], pal[t], bvh);
                            mma16816(ob[v], pa[t],  bvl);
                        }
                    }
                }
            }
        }

        const float i10 = 1.f / l_[0][0], i11 = 1.f / l_[0][1];
        const float i20 = lam / l_[1][0], i21 = lam / l_[1][1];
        const int r0 = s0 + wm + grp, r1 = r0 + 8;
#pragma unroll
        for (int v = 0; v < 16; v++) {
            const int col = h * DV + 8 * v + 2 * tig;
            const float a0 = (o1[v][0] * i10 - o2[v][0] * i20) * ONE_MINUS_LI;
            const float a1 = (o1[v][1] * i10 - o2[v][1] * i20) * ONE_MINUS_LI;
            const float a2 = (o1[v][2] * i11 - o2[v][2] * i21) * ONE_MINUS_LI;
            const float a3 = (o1[v][3] * i11 - o2[v][3] * i21) * ONE_MINUS_LI;
            store_split2(outh, outl, (size_t)r0 * (NH * DV) + col, a0, a1);
            store_split2(outh, outl, (size_t)r1 * (NH * DV) + col, a2, a3);
        }
    }
}

// ---------------- launch ----------------
static inline void launch_split(const float* X, __nv_bfloat16* H, __nv_bfloat16* L, int n) {
    const int n4 = n / 4;
    split_kernel<<<(n4 + 255) / 256, 256>>>(X, H, L, n4);
}

extern "C" void kernel_launch(void* const* d_in, const int* in_sizes, int n_in,
                              void* d_out, int out_size)
{
    const float* x     = (const float*)d_in[0];
    const float* wq_a  = (const float*)d_in[1];
    const float* wq_b  = (const float*)d_in[2];
    const float* wkv_a = (const float*)d_in[3];
    const float* wkv_b = (const float*)d_in[4];
    const float* wo    = (const float*)d_in[5];
    const float* lqn   = (const float*)d_in[6];
    const float* lqr   = (const float*)d_in[7];
    const float* lkn   = (const float*)d_in[8];
    const float* lkr   = (const float*)d_in[9];
    const float* fcos  = (const float*)d_in[10];
    const float* fsin  = (const float*)d_in[11];
    float* out = (float*)d_out;

    float *qb, *kvf, *kvb, *kpe, *lamp;
    cudaGetSymbolAddress((void**)&qb,   g_q);
    cudaGetSymbolAddress((void**)&kvf,  g_kvfull);
    cudaGetSymbolAddress((void**)&kvb,  g_kvb);
    cudaGetSymbolAddress((void**)&kpe,  g_kpe);
    cudaGetSymbolAddress((void**)&lamp, g_lam);

    __nv_bfloat16 *xh,*xl,*qah,*qal,*kvfh,*kvfl,*attnh,*attnl;
    __nv_bfloat16 *wqah,*wqal,*wqbh,*wqbl,*wkvah,*wkval,*wkvbh,*wkvbl,*woh,*wol;
    cudaGetSymbolAddress((void**)&xh, g_xh);     cudaGetSymbolAddress((void**)&xl, g_xl);
    cudaGetSymbolAddress((void**)&qah, g_qah);   cudaGetSymbolAddress((void**)&qal, g_qal);
    cudaGetSymbolAddress((void**)&kvfh, g_kvfh); cudaGetSymbolAddress((void**)&kvfl, g_kvfl);
    cudaGetSymbolAddress((void**)&attnh, g_attnh); cudaGetSymbolAddress((void**)&attnl, g_attnl);
    cudaGetSymbolAddress((void**)&wqah, g_wqah); cudaGetSymbolAddress((void**)&wqal, g_wqal);
    cudaGetSymbolAddress((void**)&wqbh, g_wqbh); cudaGetSymbolAddress((void**)&wqbl, g_wqbl);
    cudaGetSymbolAddress((void**)&wkvah, g_wkvah); cudaGetSymbolAddress((void**)&wkval, g_wkval);
    cudaGetSymbolAddress((void**)&wkvbh, g_wkvbh); cudaGetSymbolAddress((void**)&wkvbl, g_wkvbl);
    cudaGetSymbolAddress((void**)&woh, g_woh);   cudaGetSymbolAddress((void**)&wol, g_wol);

    // splits of inputs (wo's split is deferred until just before the final GEMM,
    // so the ncu capture window -s 5 -c 1 lands on the first gemm_bf16x3 launch)
    launch_split(x,     xh,    xl,    SEQ * DIM);
    launch_split(wq_a,  wqah,  wqal,  QLR * DIM);
    launch_split(wq_b,  wqbh,  wqbl,  NH * QKH * QLR);
    launch_split(wkv_a, wkvah, wkval, (KVLR + DR) * DIM);
    launch_split(wkv_b, wkvbh, wkvbl, NH * (DN + DV) * KVLR);

    const dim3 blk(256);
    const int gsmem = 8 * GBUF * (int)sizeof(__nv_bfloat16);   // 81920 B
    cudaFuncSetAttribute(gemm_bf16x3, cudaFuncAttributeMaxDynamicSharedMemorySize, gsmem);

    gemm_bf16x3<<<dim3(QLR / 128, SEQ / 128), blk, gsmem>>>(
        xh, xl, wqah, wqal, nullptr, qah, qal, SEQ, QLR, DIM, DIM, DIM, QLR);
    gemm_bf16x3<<<dim3((NH * QKH) / 128, SEQ / 128), blk, gsmem>>>(
        qah, qal, wqbh, wqbl, qb, nullptr, nullptr, SEQ, NH * QKH, QLR, QLR, QLR, NH * QKH);
    gemm_bf16x3<<<dim3((KVLR + DR + 127) / 128, SEQ / 128), blk, gsmem>>>(
        xh, xl, wkvah, wkval, kvf, kvfh, kvfl, SEQ, KVLR + DR, DIM, DIM, DIM, KVLR + DR);
    rope_kernel<<<SEQ, 256>>>(qb, kvf, kpe, fcos, fsin);
    gemm_bf16x3<<<dim3((NH * (DN + DV)) / 128, SEQ / 128), blk, gsmem>>>(
        kvfh, kvfl, wkvbh, wkvbl, kvb, nullptr, nullptr,
        SEQ, NH * (DN + DV), KVLR, KVLR + DR, KVLR, NH * (DN + DV));
    lam_kernel<<<1, 32>>>(lqn, lqr, lkn, lkr);

    const int asmem = ASMEM_ELEMS * (int)sizeof(__nv_bfloat16);
    cudaFuncSetAttribute(attn_mma_kernel, cudaFuncAttributeMaxDynamicSharedMemorySize, asmem);
    attn_mma_kernel<<<dim3(8, NH), 256, asmem>>>(qb, kvb, kpe, attnh, attnl, lamp);

    launch_split(wo, woh, wol, DIM * NH * DV);
    gemm_bf16x3<<<dim3(DIM / 128, SEQ / 128), blk, gsmem>>>(
        attnh, attnl, woh, wol, out, nullptr, nullptr, SEQ, DIM, DIM, DIM, DIM, DIM);
}

// round 12
// speedup vs baseline: 3.3999x; 1.2219x over previous
#include <cuda_runtime.h>
#include <cuda_bf16.h>
#include <math.h>

#define SEQ   2048
#define DIM   2048
#define NH    16
#define QLR   768
#define KVLR  512
#define DN    128
#define DR    64
#define DV    128
#define QKH   192
#define HALF  96

#define SCALEF 0.0721687836487032f           // 192^-0.5
#define LAMBDA_INIT_F 0.556058204155754f     // 0.8 - 0.6*exp(-0.9)
#define ONE_MINUS_LI  0.443941795844246f

// ---------------- scratch (no allocations allowed) ----------------
__device__ float g_q[SEQ * NH * QKH];        // q (roped in place)
__device__ float g_kvfull[SEQ * (KVLR + DR)];
__device__ float g_kvb[SEQ * NH * (DN + DV)];
__device__ float g_kpe[SEQ * DR];
__device__ float g_lam;

// bf16 hi/lo operand buffers
__device__ __nv_bfloat16 g_xh[SEQ * DIM],     g_xl[SEQ * DIM];
__device__ __nv_bfloat16 g_qah[SEQ * QLR],    g_qal[SEQ * QLR];
__device__ __nv_bfloat16 g_kvfh[SEQ * (KVLR + DR)], g_kvfl[SEQ * (KVLR + DR)];
__device__ __nv_bfloat16 g_attnh[SEQ * NH * DV],    g_attnl[SEQ * NH * DV];
__device__ __nv_bfloat16 g_wqah[QLR * DIM],   g_wqal[QLR * DIM];
__device__ __nv_bfloat16 g_wqbh[NH * QKH * QLR], g_wqbl[NH * QKH * QLR];
__device__ __nv_bfloat16 g_wkvah[(KVLR + DR) * DIM], g_wkval[(KVLR + DR) * DIM];
__device__ __nv_bfloat16 g_wkvbh[NH * (DN + DV) * KVLR], g_wkvbl[NH * (DN + DV) * KVLR];
__device__ __nv_bfloat16 g_woh[DIM * NH * DV], g_wol[DIM * NH * DV];

// ---------------- helpers ----------------
__device__ __forceinline__ void mma16816(float* d, const unsigned* a, const unsigned* b) {
    asm volatile(
        "mma.sync.aligned.m16n8k16.row.col.f32.bf16.bf16.f32 "
        "{%0,%1,%2,%3},{%4,%5,%6,%7},{%8,%9},{%0,%1,%2,%3};\n"
        : "+f"(d[0]), "+f"(d[1]), "+f"(d[2]), "+f"(d[3])
        : "r"(a[0]), "r"(a[1]), "r"(a[2]), "r"(a[3]), "r"(b[0]), "r"(b[1]));
}

__device__ __forceinline__ void ldsm4(unsigned* r, unsigned addr) {
    asm volatile("ldmatrix.sync.aligned.m8n8.x4.shared.b16 {%0,%1,%2,%3}, [%4];"
                 : "=r"(r[0]), "=r"(r[1]), "=r"(r[2]), "=r"(r[3]) : "r"(addr));
}
__device__ __forceinline__ void ldsm2(unsigned* r, unsigned addr) {
    asm volatile("ldmatrix.sync.aligned.m8n8.x2.shared.b16 {%0,%1}, [%2];"
                 : "=r"(r[0]), "=r"(r[1]) : "r"(addr));
}

__device__ __forceinline__ void store_split2(__nv_bfloat16* H, __nv_bfloat16* L,
                                             size_t off, float x, float y) {
    __nv_bfloat16 hx = __float2bfloat16(x), hy = __float2bfloat16(y);
    float rx = x - __bfloat162float(hx), ry = y - __bfloat162float(hy);
    __nv_bfloat162 hv, lv;
    hv.x = hx; hv.y = hy;
    lv.x = __float2bfloat16(rx); lv.y = __float2bfloat16(ry);
    *(__nv_bfloat162*)&H[off] = hv;
    *(__nv_bfloat162*)&L[off] = lv;
}

__device__ __forceinline__ unsigned packbf(float a, float b) {
    __nv_bfloat162 t = __floats2bfloat162_rn(a, b);
    return *(unsigned*)&t;
}

__device__ __forceinline__ void packsplit(float a, float b, unsigned& h, unsigned& l) {
    __nv_bfloat16 ha = __float2bfloat16(a), hb = __float2bfloat16(b);
    __nv_bfloat162 hv; hv.x = ha; hv.y = hb;
    h = *(unsigned*)&hv;
    l = packbf(a - __bfloat162float(ha), b - __bfloat162float(hb));
}

__device__ __forceinline__ void cpasync16(unsigned smem_addr, const void* gptr, int srcsize) {
    asm volatile("cp.async.cg.shared.global [%0], [%1], 16, %2;\n"
                 :: "r"(smem_addr), "l"(gptr), "r"(srcsize));
}
__device__ __forceinline__ void cpcommit() {
    asm volatile("cp.async.commit_group;\n");
}
__device__ __forceinline__ void cpwait1() {
    asm volatile("cp.async.wait_group 1;\n");
}

// ---------------- fp32 -> bf16 hi/lo split ----------------
__global__ void split_kernel(const float* __restrict__ X,
                             __nv_bfloat16* __restrict__ H,
                             __nv_bfloat16* __restrict__ L, int n4) {
    int i = blockIdx.x * blockDim.x + threadIdx.x;
    if (i < n4) {
        float4 v = ((const float4*)X)[i];
        store_split2(H, L, (size_t)i * 4, v.x, v.y);
        store_split2(H, L, (size_t)i * 4 + 2, v.z, v.w);
    }
}

// ---------------- tensor-core GEMM with cp.async double buffering + ldmatrix ----------------
// C[M,N] = A[M,K] @ B[N,K]^T ; bf16x3 fp32-emulation; 128x128 tile, BK=32, 2 stages.
#define GBUF (128 * 40)

__global__ __launch_bounds__(256) void gemm_bf16x3(
    const __nv_bfloat16* __restrict__ Ah, const __nv_bfloat16* __restrict__ Al,
    const __nv_bfloat16* __restrict__ Bh, const __nv_bfloat16* __restrict__ Bl,
    float* __restrict__ C, __nv_bfloat16* __restrict__ Ch, __nv_bfloat16* __restrict__ Cl,
    int M, int N, int K, int lda, int ldb, int ldc)
{
    extern __shared__ __align__(16) __nv_bfloat16 gs[];  // 8 buffers: [stage][Ah,Al,Bh,Bl]

    const int tid  = threadIdx.x;
    const int m0   = blockIdx.y * 128;
    const int n0   = blockIdx.x * 128;
    const int lane = tid & 31;
    const int warp = tid >> 5;
    const int wm   = (warp >> 2) * 64;
    const int wn   = (warp & 3) * 32;
    const int grp  = lane >> 2;
    const int qp   = lane & 3;

    float acc[4][4][4];
#pragma unroll
    for (int f = 0; f < 4; f++)
#pragma unroll
        for (int g = 0; g < 4; g++)
#pragma unroll
            for (int e = 0; e < 4; e++) acc[f][g][e] = 0.f;

    const unsigned gs_base = (unsigned)__cvta_generic_to_shared(gs);

    auto issue_stage = [&](int s, int kt) {
        const unsigned sbase = gs_base + (unsigned)(s * 4 * GBUF) * 2u;
#pragma unroll
        for (int i = 0; i < 4; i++) {
            const int c = tid + i * 256;           // A chunks
            const int halfb = c >> 9;
            const int w = c & 511;
            const int row = w >> 2, kc = (w & 3) * 8;
            const __nv_bfloat16* src = (halfb ? Al : Ah) + (size_t)(m0 + row) * lda + kt + kc;
            const unsigned dst = sbase + (unsigned)(halfb * GBUF + row * 40 + kc) * 2u;
            cpasync16(dst, src, 16);
        }
#pragma unroll
        for (int i = 0; i < 4; i++) {
            const int c = tid + i * 256;           // B chunks
            const int halfb = c >> 9;
            const int w = c & 511;
            const int row = w >> 2, kc = (w & 3) * 8;
            const __nv_bfloat16* src = (halfb ? Bl : Bh) + (size_t)(n0 + row) * ldb + kt + kc;
            const unsigned dst = sbase + (unsigned)((2 + halfb) * GBUF + row * 40 + kc) * 2u;
            cpasync16(dst, src, (n0 + row < N) ? 16 : 0);
        }
        cpcommit();
    };

    issue_stage(0, 0);

    // ldmatrix per-lane source coordinates (constant across iterations)
    const int arow = lane & 15;                 // A: 16 rows, two k-halves
    const int acol = (lane >> 4) * 8;
    const int brow = lane & 7;                  // B: 8 rows, two k-halves (lanes 0-15)
    const int bcol = ((lane >> 3) & 1) * 8;

    int s = 0;
    for (int kt = 0; kt < K; kt += 32, s ^= 1) {
        if (kt + 32 < K) issue_stage(s ^ 1, kt + 32);
        else cpcommit();                 // keep group-count accounting uniform
        cpwait1();                       // stage s resident
        __syncthreads();

        const unsigned sAh_a = gs_base + (unsigned)((s * 4 + 0) * GBUF) * 2u;
        const unsigned sAl_a = gs_base + (unsigned)((s * 4 + 1) * GBUF) * 2u;
        const unsigned sBh_a = gs_base + (unsigned)((s * 4 + 2) * GBUF) * 2u;
        const unsigned sBl_a = gs_base + (unsigned)((s * 4 + 3) * GBUF) * 2u;

#pragma unroll
        for (int kk = 0; kk < 32; kk += 16) {
            unsigned ah[4][4], al[4][4], bh[4][2], bl[4][2];
#pragma unroll
            for (int f = 0; f < 4; f++) {
                const unsigned o = (unsigned)(((wm + f * 16 + arow) * 40 + kk + acol) * 2);
                ldsm4(ah[f], sAh_a + o);
                ldsm4(al[f], sAl_a + o);
            }
#pragma unroll
            for (int g = 0; g < 4; g++) {
                const unsigned o = (unsigned)(((wn + g * 8 + brow) * 40 + kk + bcol) * 2);
                ldsm2(bh[g], sBh_a + o);
                ldsm2(bl[g], sBl_a + o);
            }
#pragma unroll
            for (int f = 0; f < 4; f++)
#pragma unroll
                for (int g = 0; g < 4; g++) {
                    mma16816(acc[f][g], ah[f], bh[g]);
                    mma16816(acc[f][g], ah[f], bl[g]);
                    mma16816(acc[f][g], al[f], bh[g]);
                }
        }
        __syncthreads();   // compute on stage s done before next prefetch overwrites it
    }

#pragma unroll
    for (int f = 0; f < 4; f++)
#pragma unroll
        for (int g = 0; g < 4; g++) {
            const int r0  = m0 + wm + f * 16 + grp;
            const int col = n0 + wn + g * 8 + qp * 2;
            if (col < N) {
                const float* a = acc[f][g];
                if (C) {
                    *(float2*)&C[(size_t)r0 * ldc + col]       = make_float2(a[0], a[1]);
                    *(float2*)&C[(size_t)(r0 + 8) * ldc + col] = make_float2(a[2], a[3]);
                }
                if (Ch) {
                    store_split2(Ch, Cl, (size_t)r0 * ldc + col, a[0], a[1]);
                    store_split2(Ch, Cl, (size_t)(r0 + 8) * ldc + col, a[2], a[3]);
                }
            }
        }
}

// ---------------- RoPE (interleaved pairs) ----------------
__global__ void rope_kernel(float* __restrict__ q, const float* __restrict__ kvfull,
                            float* __restrict__ kpe,
                            const float* __restrict__ cosb, const float* __restrict__ sinb)
{
    const int s = blockIdx.x;
    for (int idx = threadIdx.x; idx < NH * 32 + 32; idx += blockDim.x) {
        if (idx < NH * 32) {
            const int h = idx >> 5, p = idx & 31;
            const float c = cosb[s * 32 + p], sn = sinb[s * 32 + p];
            float* base = q + (long)s * (NH * QKH) + h * QKH + DN;
            const float xr = base[2 * p], xi = base[2 * p + 1];
            base[2 * p]     = xr * c - xi * sn;
            base[2 * p + 1] = xr * sn + xi * c;
        } else {
            const int p = idx - NH * 32;
            const float c = cosb[s * 32 + p], sn = sinb[s * 32 + p];
            const float* kb = kvfull + (long)s * (KVLR + DR) + KVLR;
            const float xr = kb[2 * p], xi = kb[2 * p + 1];
            kpe[s * DR + 2 * p]     = xr * c - xi * sn;
            kpe[s * DR + 2 * p + 1] = xr * sn + xi * c;
        }
    }
}

// ---------------- lambda scalar ----------------
__global__ void lam_kernel(const float* __restrict__ lqn, const float* __restrict__ lqr,
                           const float* __restrict__ lkn, const float* __restrict__ lkr)
{
    if (threadIdx.x == 0) {
        float d1 = 0.f, d2 = 0.f;
        for (int i = 0; i < DN; i++) d1 += lqn[i] * lkn[i];
        for (int i = 0; i < DR; i++) d2 += lqr[i] * lkr[i];
        g_lam = expf(d1) - expf(d2) + LAMBDA_INIT_F;
    }
}

// ---------------- tensor-core dual-softmax flash attention ----------------
// Same structure as R7/R10; K/V/Q tile loads vectorized to float4.
#define ABQ 128
#define ABK 64
#define KSTR 200
#define VSTR 72
#define ASMEM_ELEMS (2*ABQ*KSTR + 2*ABK*KSTR + 2*DV*VSTR)

__global__ __launch_bounds__(256, 1) void attn_mma_kernel(
    const float* __restrict__ q, const float* __restrict__ kvb,
    const float* __restrict__ kpe,
    __nv_bfloat16* __restrict__ outh, __nv_bfloat16* __restrict__ outl,
    const float* __restrict__ lamp)
{
    extern __shared__ __nv_bfloat16 sb[];
    __nv_bfloat16* Qh  = sb;
    __nv_bfloat16* Ql  = Qh  + ABQ * KSTR;
    __nv_bfloat16* Kh  = Ql  + ABQ * KSTR;
    __nv_bfloat16* Kl  = Kh  + ABK * KSTR;
    __nv_bfloat16* VTh = Kl  + ABK * KSTR;
    __nv_bfloat16* VTl = VTh + DV * VSTR;

    const int tid  = threadIdx.x;
    const int lane = tid & 31;
    const int warp = tid >> 5;
    const int grp  = lane >> 2;
    const int tig  = lane & 3;
    const int wm   = warp * 16;
    const int h    = blockIdx.y;
    const float lam = *lamp;

    for (int half = 0; half < 2; half++) {
        const int qi = (half == 0) ? (int)blockIdx.x : (15 - (int)blockIdx.x);
        const int s0 = qi * ABQ;

        __syncthreads();   // previous half's compute fully done before smem rewrite

        // ---- load Q tile (fp32 -> hi/lo bf16), float4 loads ----
        {
            const int r  = tid >> 1;
            const int d0 = (tid & 1) * 96;
            const float4* src4 =
                (const float4*)(q + (size_t)(s0 + r) * (NH * QKH) + h * QKH + d0);
#pragma unroll
            for (int i = 0; i < 24; i++) {
                const float4 v = src4[i];
                const size_t o = (size_t)r * KSTR + d0 + i * 4;
                store_split2(Qh, Ql, o,     v.x, v.y);
                store_split2(Qh, Ql, o + 2, v.z, v.w);
            }
        }

        float o1[16][4], o2[16][4];
#pragma unroll
        for (int v = 0; v < 16; v++)
#pragma unroll
            for (int e = 0; e < 4; e++) { o1[v][e] = 0.f; o2[v][e] = 0.f; }
        float m_[2][2] = {{-1e30f, -1e30f}, {-1e30f, -1e30f}};
        float l_[2][2] = {{0.f, 0.f}, {0.f, 0.f}};

        const int ntiles = s0 / ABK + 2;
        for (int tix = 0; tix < ntiles; tix++) {
            const int t0 = tix * ABK;
            if (tix > 0) __syncthreads();   // compute done before K/V rewrite
            // ---- load K tile (192 dims -> hi/lo) and V^T (hi/lo), float4 loads ----
            {
                const int k  = tid >> 2;
                const int j4 = (tid & 3) * 12;   // first of 12 float4s of the K row
                const float4* kn4 =
                    (const float4*)(kvb + (size_t)(t0 + k) * (NH * 256) + h * 256);
                const float4* kp4 = (const float4*)(kpe + (size_t)(t0 + k) * DR);
#pragma unroll
                for (int i = 0; i < 12; i++) {
                    const int f4 = j4 + i;            // 0..47 over [kn 0:128 | kp 0:64]
                    const float4 v = (f4 < 32) ? kn4[f4] : kp4[f4 - 32];
                    const size_t o = (size_t)k * KSTR + f4 * 4;
                    store_split2(Kh, Kl, o,     v.x, v.y);
                    store_split2(Kh, Kl, o + 2, v.z, v.w);
                }
                const int vd0 = (tid & 3) * 32;
                const float4* vv4 = (const float4*)(kvb +
                    (size_t)(t0 + k) * (NH * 256) + h * 256 + 128 + vd0);
#pragma unroll
                for (int i = 0; i < 8; i++) {
                    const float4 v = vv4[i];
                    const float vals[4] = {v.x, v.y, v.z, v.w};
#pragma unroll
                    for (int e = 0; e < 4; e++) {
                        const int d = vd0 + i * 4 + e;
                        const __nv_bfloat16 hv = __float2bfloat16(vals[e]);
                        VTh[d * VSTR + k] = hv;
                        VTl[d * VSTR + k] =
                            __float2bfloat16(vals[e] - __bfloat162float(hv));
                    }
                }
            }
            __syncthreads();

            if (t0 <= s0 + wm + 15) {       // warp-uniform skip of fully-masked tiles
#pragma unroll
                for (int br = 0; br < 2; br++) {
                    const int kb = br * HALF;
                    float acc[8][4];
#pragma unroll
                    for (int j = 0; j < 8; j++)
#pragma unroll
                        for (int e = 0; e < 4; e++) acc[j][e] = 0.f;

#pragma unroll
                    for (int t = 0; t < 6; t++) {
                        const int kk = kb + t * 16;
                        unsigned ah[4], al[4];
                        const int qo = (wm + grp) * KSTR + kk + 2 * tig;
                        ah[0] = *(const unsigned*)&Qh[qo];
                        ah[1] = *(const unsigned*)&Qh[qo + 8 * KSTR];
                        ah[2] = *(const unsigned*)&Qh[qo + 8];
                        ah[3] = *(const unsigned*)&Qh[qo + 8 * KSTR + 8];
                        al[0] = *(const unsigned*)&Ql[qo];
                        al[1] = *(const unsigned*)&Ql[qo + 8 * KSTR];
                        al[2] = *(const unsigned*)&Ql[qo + 8];
                        al[3] = *(const unsigned*)&Ql[qo + 8 * KSTR + 8];
#pragma unroll
                        for (int j = 0; j < 8; j++) {
                            unsigned bh[2], bl[2];
                            const int ko = (8 * j + grp) * KSTR + kk + 2 * tig;
                            bh[0] = *(const unsigned*)&Kh[ko];
                            bh[1] = *(const unsigned*)&Kh[ko + 8];
                            bl[0] = *(const unsigned*)&Kl[ko];
                            bl[1] = *(const unsigned*)&Kl[ko + 8];
                            mma16816(acc[j], ah, bh);
                            mma16816(acc[j], ah, bl);
                            mma16816(acc[j], al, bh);
                        }
                    }

                    const int r0 = s0 + wm + grp, r1 = r0 + 8;
#pragma unroll
                    for (int j = 0; j < 8; j++)
#pragma unroll
                        for (int e = 0; e < 4; e++) {
                            const int key = t0 + 8 * j + 2 * tig + (e & 1);
                            const int row = (e < 2) ? r0 : r1;
                            float v = fminf(fmaxf(acc[j][e] * SCALEF, -100.f), 100.f);
                            acc[j][e] = (key > row) ? -1e9f : v;
                        }

                    float mx0 = -1e30f, mx1 = -1e30f;
#pragma unroll
                    for (int j = 0; j < 8; j++) {
                        mx0 = fmaxf(mx0, fmaxf(acc[j][0], acc[j][1]));
                        mx1 = fmaxf(mx1, fmaxf(acc[j][2], acc[j][3]));
                    }
                    mx0 = fmaxf(mx0, __shfl_xor_sync(0xffffffffu, mx0, 1));
                    mx0 = fmaxf(mx0, __shfl_xor_sync(0xffffffffu, mx0, 2));
                    mx1 = fmaxf(mx1, __shfl_xor_sync(0xffffffffu, mx1, 1));
                    mx1 = fmaxf(mx1, __shfl_xor_sync(0xffffffffu, mx1, 2));

                    const float mo0 = m_[br][0], mo1 = m_[br][1];
                    const float mn0 = fmaxf(mo0, mx0), mn1 = fmaxf(mo1, mx1);
                    const float sc0 = __expf(mo0 - mn0), sc1 = __expf(mo1 - mn1);
                    m_[br][0] = mn0; m_[br][1] = mn1;

                    float su0 = 0.f, su1 = 0.f;
#pragma unroll
                    for (int j = 0; j < 8; j++) {
                        float p0 = __expf(acc[j][0] - mn0);
                        float p1 = __expf(acc[j][1] - mn0);
                        float p2 = __expf(acc[j][2] - mn1);
                        float p3 = __expf(acc[j][3] - mn1);
                        acc[j][0] = p0; acc[j][1] = p1; acc[j][2] = p2; acc[j][3] = p3;
                        su0 += p0 + p1; su1 += p2 + p3;
                    }
                    su0 += __shfl_xor_sync(0xffffffffu, su0, 1);
                    su0 += __shfl_xor_sync(0xffffffffu, su0, 2);
                    su1 += __shfl_xor_sync(0xffffffffu, su1, 1);
                    su1 += __shfl_xor_sync(0xffffffffu, su1, 2);
                    l_[br][0] = l_[br][0] * sc0 + su0;
                    l_[br][1] = l_[br][1] * sc1 + su1;

                    float (*ob)[4] = br ? o2 : o1;
#pragma unroll
                    for (int v = 0; v < 16; v++) {
                        ob[v][0] *= sc0; ob[v][1] *= sc0;
                        ob[v][2] *= sc1; ob[v][3] *= sc1;
                    }

                    unsigned pa[4][4], pal[4][4];
#pragma unroll
                    for (int t = 0; t < 4; t++) {
                        packsplit(acc[2 * t][0],     acc[2 * t][1],     pa[t][0], pal[t][0]);
                        packsplit(acc[2 * t][2],     acc[2 * t][3],     pa[t][1], pal[t][1]);
                        packsplit(acc[2 * t + 1][0], acc[2 * t + 1][1], pa[t][2], pal[t][2]);
                        packsplit(acc[2 * t + 1][2], acc[2 * t + 1][3], pa[t][3], pal[t][3]);
                    }

#pragma unroll
                    for (int v = 0; v < 16; v++) {
#pragma unroll
                        for (int t = 0; t < 4; t++) {
                            unsigned bvh[2], bvl[2];
                            const int vo = (8 * v + grp) * VSTR + 16 * t + 2 * tig;
                            bvh[0] = *(const unsigned*)&VTh[vo];
                            bvh[1] = *(const unsigned*)&VTh[vo + 8];
                            bvl[0] = *(const unsigned*)&VTl[vo];
                            bvl[1] = *(const unsigned*)&VTl[vo + 8];
                            mma16816(ob[v], pa[t],  bvh);
                            mma16816(ob[v], pal[t], bvh);
                            mma16816(ob[v], pa[t],  bvl);
                        }
                    }
                }
            }
        }

        const float i10 = 1.f / l_[0][0], i11 = 1.f / l_[0][1];
        const float i20 = lam / l_[1][0], i21 = lam / l_[1][1];
        const int r0 = s0 + wm + grp, r1 = r0 + 8;
#pragma unroll
        for (int v = 0; v < 16; v++) {
            const int col = h * DV + 8 * v + 2 * tig;
            const float a0 = (o1[v][0] * i10 - o2[v][0] * i20) * ONE_MINUS_LI;
            const float a1 = (o1[v][1] * i10 - o2[v][1] * i20) * ONE_MINUS_LI;
            const float a2 = (o1[v][2] * i11 - o2[v][2] * i21) * ONE_MINUS_LI;
            const float a3 = (o1[v][3] * i11 - o2[v][3] * i21) * ONE_MINUS_LI;
            store_split2(outh, outl, (size_t)r0 * (NH * DV) + col, a0, a1);
            store_split2(outh, outl, (size_t)r1 * (NH * DV) + col, a2, a3);
        }
    }
}

// ---------------- launch ----------------
static inline void launch_split(const float* X, __nv_bfloat16* H, __nv_bfloat16* L, int n) {
    const int n4 = n / 4;
    split_kernel<<<(n4 + 255) / 256, 256>>>(X, H, L, n4);
}

extern "C" void kernel_launch(void* const* d_in, const int* in_sizes, int n_in,
                              void* d_out, int out_size)
{
    const float* x     = (const float*)d_in[0];
    const float* wq_a  = (const float*)d_in[1];
    const float* wq_b  = (const float*)d_in[2];
    const float* wkv_a = (const float*)d_in[3];
    const float* wkv_b = (const float*)d_in[4];
    const float* wo    = (const float*)d_in[5];
    const float* lqn   = (const float*)d_in[6];
    const float* lqr   = (const float*)d_in[7];
    const float* lkn   = (const float*)d_in[8];
    const float* lkr   = (const float*)d_in[9];
    const float* fcos  = (const float*)d_in[10];
    const float* fsin  = (const float*)d_in[11];
    float* out = (float*)d_out;

    float *qb, *kvf, *kvb, *kpe, *lamp;
    cudaGetSymbolAddress((void**)&qb,   g_q);
    cudaGetSymbolAddress((void**)&kvf,  g_kvfull);
    cudaGetSymbolAddress((void**)&kvb,  g_kvb);
    cudaGetSymbolAddress((void**)&kpe,  g_kpe);
    cudaGetSymbolAddress((void**)&lamp, g_lam);

    __nv_bfloat16 *xh,*xl,*qah,*qal,*kvfh,*kvfl,*attnh,*attnl;
    __nv_bfloat16 *wqah,*wqal,*wqbh,*wqbl,*wkvah,*wkval,*wkvbh,*wkvbl,*woh,*wol;
    cudaGetSymbolAddress((void**)&xh, g_xh);     cudaGetSymbolAddress((void**)&xl, g_xl);
    cudaGetSymbolAddress((void**)&qah, g_qah);   cudaGetSymbolAddress((void**)&qal, g_qal);
    cudaGetSymbolAddress((void**)&kvfh, g_kvfh); cudaGetSymbolAddress((void**)&kvfl, g_kvfl);
    cudaGetSymbolAddress((void**)&attnh, g_attnh); cudaGetSymbolAddress((void**)&attnl, g_attnl);
    cudaGetSymbolAddress((void**)&wqah, g_wqah); cudaGetSymbolAddress((void**)&wqal, g_wqal);
    cudaGetSymbolAddress((void**)&wqbh, g_wqbh); cudaGetSymbolAddress((void**)&wqbl, g_wqbl);
    cudaGetSymbolAddress((void**)&wkvah, g_wkvah); cudaGetSymbolAddress((void**)&wkval, g_wkval);
    cudaGetSymbolAddress((void**)&wkvbh, g_wkvbh); cudaGetSymbolAddress((void**)&wkvbl, g_wkvbl);
    cudaGetSymbolAddress((void**)&woh, g_woh);   cudaGetSymbolAddress((void**)&wol, g_wol);

    const dim3 blk(256);
    const int gsmem = 8 * GBUF * (int)sizeof(__nv_bfloat16);   // 81920 B
    cudaFuncSetAttribute(gemm_bf16x3, cudaFuncAttributeMaxDynamicSharedMemorySize, gsmem);

    // Launch order arranged so the 4th kernel launch is gemm_bf16x3 (empirically
    // the ncu capture window lands on launch #4 -> finally get a GEMM profile).
    launch_split(x,     xh,    xl,    SEQ * DIM);            // 1
    launch_split(wq_a,  wqah,  wqal,  QLR * DIM);            // 2
    launch_split(wq_b,  wqbh,  wqbl,  NH * QKH * QLR);       // 3
    gemm_bf16x3<<<dim3(QLR / 128, SEQ / 128), blk, gsmem>>>( // 4  <- profiled
        xh, xl, wqah, wqal, nullptr, qah, qal, SEQ, QLR, DIM, DIM, DIM, QLR);
    launch_split(wkv_a, wkvah, wkval, (KVLR + DR) * DIM);    // 5
    launch_split(wkv_b, wkvbh, wkvbl, NH * (DN + DV) * KVLR);// 6
    gemm_bf16x3<<<dim3((NH * QKH) / 128, SEQ / 128), blk, gsmem>>>(
        qah, qal, wqbh, wqbl, qb, nullptr, nullptr, SEQ, NH * QKH, QLR, QLR, QLR, NH * QKH);
    gemm_bf16x3<<<dim3((KVLR + DR + 127) / 128, SEQ / 128), blk, gsmem>>>(
        xh, xl, wkvah, wkval, kvf, kvfh, kvfl, SEQ, KVLR + DR, DIM, DIM, DIM, KVLR + DR);
    rope_kernel<<<SEQ, 256>>>(qb, kvf, kpe, fcos, fsin);
    gemm_bf16x3<<<dim3((NH * (DN + DV)) / 128, SEQ / 128), blk, gsmem>>>(
        kvfh, kvfl, wkvbh, wkvbl, kvb, nullptr, nullptr,
        SEQ, NH * (DN + DV), KVLR, KVLR + DR, KVLR, NH * (DN + DV));
    lam_kernel<<<1, 32>>>(lqn, lqr, lkn, lkr);

    const int asmem = ASMEM_ELEMS * (int)sizeof(__nv_bfloat16);
    cudaFuncSetAttribute(attn_mma_kernel, cudaFuncAttributeMaxDynamicSharedMemorySize, asmem);
    attn_mma_kernel<<<dim3(8, NH), 256, asmem>>>(qb, kvb, kpe, attnh, attnl, lamp);

    launch_split(wo, woh, wol, DIM * NH * DV);
    gemm_bf16x3<<<dim3(DIM / 128, SEQ / 128), blk, gsmem>>>(
        attnh, attnl, woh, wol, out, nullptr, nullptr, SEQ, DIM, DIM, DIM, DIM, DIM);
}